// round 1
// baseline (speedup 1.0000x reference)
#include <cuda_runtime.h>
#include <cuda_bf16.h>
#include <math.h>

// ---------------- problem constants ----------------
#define N_NODES 50000
#define E_EDGES 800000
#define ET (E_EDGES + N_NODES)   // edges + self loops = 850000
#define NGRAPH 64
#define NEG_SLOPE 0.2f

// ---------------- device scratch (no allocations allowed) ----------------
__device__ float g_ht [N_NODES * 256];   // GEMM output (pre-bias features)
__device__ float g_act[N_NODES * 256];   // layer activation (agg output)
__device__ float g_esrc[N_NODES * 4];
__device__ float g_edst[N_NODES * 4];
__device__ int   g_deg   [N_NODES];
__device__ int   g_rowptr[N_NODES + 1];
__device__ int   g_cursor[N_NODES];
__device__ int   g_srclist[ET];
__device__ float g_pool[NGRAPH * 64];
__device__ float g_cnt [NGRAPH];

// ---------------- init ----------------
__global__ void zero_init_kernel() {
    int i = blockIdx.x * blockDim.x + threadIdx.x;
    if (i < N_NODES) g_deg[i] = 0;
    if (i < NGRAPH * 64) g_pool[i] = 0.f;
    if (i < NGRAPH) g_cnt[i] = 0.f;
}

// ---------------- CSR build (by destination) ----------------
__global__ void count_deg_kernel(const int* __restrict__ ei) {
    int e = blockIdx.x * blockDim.x + threadIdx.x;
    if (e >= ET) return;
    int d = (e < E_EDGES) ? ei[E_EDGES + e] : (e - E_EDGES);
    atomicAdd(&g_deg[d], 1);
}

__global__ void scan_kernel() {
    __shared__ int part[1024];
    const int PER = (N_NODES + 1023) / 1024;   // 49
    int t = threadIdx.x;
    int base = t * PER;
    int s = 0;
    for (int i = 0; i < PER; i++) {
        int idx = base + i;
        if (idx < N_NODES) s += g_deg[idx];
    }
    part[t] = s;
    __syncthreads();
    // Hillis-Steele inclusive scan over 1024 partials
    for (int o = 1; o < 1024; o <<= 1) {
        int v = (t >= o) ? part[t - o] : 0;
        __syncthreads();
        part[t] += v;
        __syncthreads();
    }
    int run = (t == 0) ? 0 : part[t - 1];
    for (int i = 0; i < PER; i++) {
        int idx = base + i;
        if (idx < N_NODES) {
            g_rowptr[idx] = run;
            g_cursor[idx] = run;
            run += g_deg[idx];
        }
    }
    if (t == 1023) g_rowptr[N_NODES] = part[1023];
}

__global__ void fill_csr_kernel(const int* __restrict__ ei) {
    int e = blockIdx.x * blockDim.x + threadIdx.x;
    if (e >= ET) return;
    int s, d;
    if (e < E_EDGES) { s = ei[e]; d = ei[E_EDGES + e]; }
    else             { s = e - E_EDGES; d = s; }
    int pos = atomicAdd(&g_cursor[d], 1);
    g_srclist[pos] = s;
}

// ---------------- SGEMM: C[M,Nd] = A[M,K] @ B[K,Nd] ----------------
// BM=BN=64, BK=16, 256 threads, 4x4 per thread.
__global__ void sgemm_kernel(const float* __restrict__ A,
                             const float* __restrict__ B,
                             float* __restrict__ C,
                             int M, int K, int Nd) {
    __shared__ float As[16][65];
    __shared__ float Bs[16][64];
    int tid = threadIdx.x;
    int tx = tid & 15, ty = tid >> 4;
    int row0 = blockIdx.y * 64;
    int col0 = blockIdx.x * 64;
    float acc[4][4] = {};

    for (int k0 = 0; k0 < K; k0 += 16) {
#pragma unroll
        for (int i = 0; i < 4; i++) {
            int idx = tid + i * 256;
            int m = idx >> 4, kk = idx & 15;
            int gr = row0 + m;
            As[kk][m] = (gr < M) ? A[gr * K + k0 + kk] : 0.f;
        }
#pragma unroll
        for (int i = 0; i < 4; i++) {
            int idx = tid + i * 256;
            int n = idx & 63, kk = idx >> 6;
            Bs[kk][n] = B[(k0 + kk) * Nd + col0 + n];
        }
        __syncthreads();
#pragma unroll
        for (int kk = 0; kk < 16; kk++) {
            float a[4], b[4];
#pragma unroll
            for (int i = 0; i < 4; i++) a[i] = As[kk][ty * 4 + i];
#pragma unroll
            for (int j = 0; j < 4; j++) b[j] = Bs[kk][tx * 4 + j];
#pragma unroll
            for (int i = 0; i < 4; i++)
#pragma unroll
                for (int j = 0; j < 4; j++)
                    acc[i][j] = fmaf(a[i], b[j], acc[i][j]);
        }
        __syncthreads();
    }
#pragma unroll
    for (int i = 0; i < 4; i++) {
        int gr = row0 + ty * 4 + i;
        if (gr < M) {
#pragma unroll
            for (int j = 0; j < 4; j++)
                C[gr * Nd + col0 + tx * 4 + j] = acc[i][j];
        }
    }
}

// ---------------- attention coefficients: esrc/edst per node per head ----------------
// HC threads per block, one node per block. a_src/a_dst are [H,C] flattened = channel index.
template <int HC, int H>
__global__ void attn_coef_kernel(const float* __restrict__ ht,
                                 const float* __restrict__ asrc,
                                 const float* __restrict__ adst) {
    int n = blockIdx.x;
    int t = threadIdx.x;
    float hv = ht[n * HC + t];
    float ps = hv * asrc[t];
    float pd = hv * adst[t];
#pragma unroll
    for (int o = 16; o > 0; o >>= 1) {
        ps += __shfl_down_sync(0xFFFFFFFFu, ps, o);
        pd += __shfl_down_sync(0xFFFFFFFFu, pd, o);
    }
    __shared__ float ss[HC / 32];
    __shared__ float sd[HC / 32];
    if ((t & 31) == 0) { ss[t >> 5] = ps; sd[t >> 5] = pd; }
    __syncthreads();
    if (t < H) {   // each head = 2 warps of 32 (C=64)
        g_esrc[n * H + t] = ss[2 * t] + ss[2 * t + 1];
        g_edst[n * H + t] = sd[2 * t] + sd[2 * t + 1];
    }
}

// ---------------- fused gather softmax + aggregation + bias (+relu) ----------------
// Per dst node: pass1 max per head, pass2 accumulate exp*h and denom, normalize.
// HC = H*64 channels. TPG = HC/4 threads per node (float4 per thread). blockDim = 128.
template <int H, bool RELU>
__global__ void gat_agg_kernel(const float* __restrict__ ht,
                               const float* __restrict__ bias,
                               float* __restrict__ outbuf) {
    constexpr int HC  = H * 64;
    constexpr int TPG = HC / 4;
    constexpr int NPB = 128 / TPG;
    int node = blockIdx.x * NPB + threadIdx.x / TPG;
    if (node >= N_NODES) return;
    int t = threadIdx.x % TPG;         // owns channels [t*4, t*4+4)
    int head = (t * 4) >> 6;

    int beg = g_rowptr[node];
    int end = g_rowptr[node + 1];
    float ed = g_edst[node * H + head];

    // pass 1: max
    float m = -INFINITY;
    for (int i = beg; i < end; i++) {
        int s = g_srclist[i];
        float e = g_esrc[s * H + head] + ed;
        e = (e > 0.f) ? e : NEG_SLOPE * e;
        m = fmaxf(m, e);
    }

    // pass 2: accumulate
    float4 acc = make_float4(0.f, 0.f, 0.f, 0.f);
    float denom = 0.f;
    const float4* htv = reinterpret_cast<const float4*>(ht);
    for (int i = beg; i < end; i++) {
        int s = g_srclist[i];
        float e = g_esrc[s * H + head] + ed;
        e = (e > 0.f) ? e : NEG_SLOPE * e;
        float ex = __expf(e - m);
        denom += ex;
        float4 hv = htv[s * TPG + t];
        acc.x = fmaf(ex, hv.x, acc.x);
        acc.y = fmaf(ex, hv.y, acc.y);
        acc.z = fmaf(ex, hv.z, acc.z);
        acc.w = fmaf(ex, hv.w, acc.w);
    }

    float inv = 1.f / (denom + 1e-16f);
    int c0 = t * 4;
    float4 r;
    r.x = acc.x * inv + bias[c0 + 0];
    r.y = acc.y * inv + bias[c0 + 1];
    r.z = acc.z * inv + bias[c0 + 2];
    r.w = acc.w * inv + bias[c0 + 3];
    if (RELU) {
        r.x = fmaxf(r.x, 0.f); r.y = fmaxf(r.y, 0.f);
        r.z = fmaxf(r.z, 0.f); r.w = fmaxf(r.w, 0.f);
    }
    reinterpret_cast<float4*>(outbuf)[node * TPG + t] = r;
}

// ---------------- pooling ----------------
__global__ void pool_kernel(const int* __restrict__ batch,
                            const float* __restrict__ act) {
    int gid = blockIdx.x * blockDim.x + threadIdx.x;
    if (gid >= N_NODES * 64) return;
    int n = gid >> 6, c = gid & 63;
    int g = batch[n];
    atomicAdd(&g_pool[g * 64 + c], act[n * 64 + c]);
    if (c == 0) atomicAdd(&g_cnt[g], 1.f);
}

__global__ void finalize_kernel(const float* __restrict__ lin_w,
                                const float* __restrict__ lin_b,
                                float* __restrict__ out) {
    int g = threadIdx.x;   // 64 threads
    float cnt = fmaxf(g_cnt[g], 1.f);
    float s = 0.f;
    for (int c = 0; c < 64; c++)
        s += g_pool[g * 64 + c] * lin_w[c];
    out[g] = s / cnt + lin_b[0];
}

// ---------------- launch ----------------
extern "C" void kernel_launch(void* const* d_in, const int* in_sizes, int n_in,
                              void* d_out, int out_size) {
    (void)in_sizes; (void)n_in; (void)out_size;
    const float* x      = (const float*)d_in[0];
    const int*   ei     = (const int*)  d_in[1];
    const int*   batch  = (const int*)  d_in[2];
    const float* W0     = (const float*)d_in[3];
    const float* asrc0  = (const float*)d_in[4];
    const float* adst0  = (const float*)d_in[5];
    const float* b0     = (const float*)d_in[6];
    const float* W1     = (const float*)d_in[7];
    const float* asrc1  = (const float*)d_in[8];
    const float* adst1  = (const float*)d_in[9];
    const float* b1     = (const float*)d_in[10];
    const float* W2     = (const float*)d_in[11];
    const float* asrc2  = (const float*)d_in[12];
    const float* adst2  = (const float*)d_in[13];
    const float* b2     = (const float*)d_in[14];
    const float* lin_w  = (const float*)d_in[15];
    const float* lin_b  = (const float*)d_in[16];
    float* out = (float*)d_out;

    void *p_ht_v, *p_act_v;
    cudaGetSymbolAddress(&p_ht_v, g_ht);
    cudaGetSymbolAddress(&p_act_v, g_act);
    float* p_ht  = (float*)p_ht_v;
    float* p_act = (float*)p_act_v;

    // init + CSR build (reused by all 3 layers)
    zero_init_kernel<<<(N_NODES + 255) / 256, 256>>>();
    count_deg_kernel<<<(ET + 255) / 256, 256>>>(ei);
    scan_kernel<<<1, 1024>>>();
    fill_csr_kernel<<<(ET + 255) / 256, 256>>>(ei);

    dim3 gemm_blk(256);
    // ----- layer 0: 128 -> 256 (4 heads x 64, concat, relu) -----
    {
        dim3 grid(256 / 64, (N_NODES + 63) / 64);
        sgemm_kernel<<<grid, gemm_blk>>>(x, W0, p_ht, N_NODES, 128, 256);
        attn_coef_kernel<256, 4><<<N_NODES, 256>>>(p_ht, asrc0, adst0);
        int nb = (N_NODES + 1) / 2;   // NPB=2 for H=4
        gat_agg_kernel<4, true><<<nb, 128>>>(p_ht, b0, p_act);
    }
    // ----- layer 1: 256 -> 256 (4 heads x 64, concat, relu) -----
    {
        dim3 grid(256 / 64, (N_NODES + 63) / 64);
        sgemm_kernel<<<grid, gemm_blk>>>(p_act, W1, p_ht, N_NODES, 256, 256);
        attn_coef_kernel<256, 4><<<N_NODES, 256>>>(p_ht, asrc1, adst1);
        int nb = (N_NODES + 1) / 2;
        gat_agg_kernel<4, true><<<nb, 128>>>(p_ht, b1, p_act);
    }
    // ----- layer 2: 256 -> 64 (1 head, no relu) -----
    {
        dim3 grid(64 / 64, (N_NODES + 63) / 64);
        sgemm_kernel<<<grid, gemm_blk>>>(p_act, W2, p_ht, N_NODES, 256, 64);
        attn_coef_kernel<64, 1><<<N_NODES, 64>>>(p_ht, asrc2, adst2);
        int nb = (N_NODES + 7) / 8;   // NPB=8 for H=1
        gat_agg_kernel<1, false><<<nb, 128>>>(p_ht, b2, p_act);
    }
    // ----- global mean pool + linear -----
    pool_kernel<<<(N_NODES * 64 + 255) / 256, 256>>>(batch, p_act);
    finalize_kernel<<<1, 64>>>(lin_w, lin_b, out);
}

// round 2
// speedup vs baseline: 1.1417x; 1.1417x over previous
#include <cuda_runtime.h>
#include <cuda_bf16.h>
#include <math.h>

// ---------------- problem constants ----------------
#define N_NODES 50000
#define E_EDGES 800000
#define ET (E_EDGES + N_NODES)   // edges + self loops = 850000
#define NGRAPH 64
#define NEG_SLOPE 0.2f

// ---------------- device scratch ----------------
__device__ float g_ht [N_NODES * 256];
__device__ float g_act[N_NODES * 256];
__device__ float g_esrc[N_NODES * 4];
__device__ float g_edst[N_NODES * 4];
__device__ int   g_deg   [N_NODES];
__device__ int   g_rowptr[N_NODES + 1];
__device__ int   g_cursor[N_NODES];
__device__ int   g_srclist[ET];
__device__ float g_pool[NGRAPH * 64];
__device__ float g_cnt [NGRAPH];

// ---------------- CSR build (by destination) ----------------
__global__ void count_deg_kernel(const int* __restrict__ ei) {
    int e = blockIdx.x * blockDim.x + threadIdx.x;
    if (e >= ET) return;
    int d = (e < E_EDGES) ? ei[E_EDGES + e] : (e - E_EDGES);
    atomicAdd(&g_deg[d], 1);
}

__global__ void scan_kernel() {
    __shared__ int part[1024];
    const int PER = (N_NODES + 1023) / 1024;   // 49
    int t = threadIdx.x;
    int base = t * PER;
    int s = 0;
    for (int i = 0; i < PER; i++) {
        int idx = base + i;
        if (idx < N_NODES) s += g_deg[idx];
    }
    part[t] = s;
    __syncthreads();
    for (int o = 1; o < 1024; o <<= 1) {
        int v = (t >= o) ? part[t - o] : 0;
        __syncthreads();
        part[t] += v;
        __syncthreads();
    }
    int run = (t == 0) ? 0 : part[t - 1];
    for (int i = 0; i < PER; i++) {
        int idx = base + i;
        if (idx < N_NODES) {
            g_rowptr[idx] = run;
            g_cursor[idx] = run;
            run += g_deg[idx];
        }
    }
    if (t == 1023) g_rowptr[N_NODES] = part[1023];
}

__global__ void fill_csr_kernel(const int* __restrict__ ei) {
    int e = blockIdx.x * blockDim.x + threadIdx.x;
    if (e >= ET) return;
    int s, d;
    if (e < E_EDGES) { s = ei[e]; d = ei[E_EDGES + e]; }
    else             { s = e - E_EDGES; d = s; }
    int pos = atomicAdd(&g_cursor[d], 1);
    g_srclist[pos] = s;
}

// ---------------- 3xTF32 tensor-core GEMM ----------------
// C[M,Nd] = A[M,K] @ B[K,Nd], fp32 in/out, near-fp32 precision via hi/lo split.
// BM=128, BN=64, BK=32, 256 threads = 8 warps (4 in M x 2 in N), warp tile 32x32.

__device__ __forceinline__ unsigned f2tf32(float f) {
    unsigned r;
    asm("cvt.rna.tf32.f32 %0, %1;" : "=r"(r) : "f"(f));
    return r;
}

__device__ __forceinline__ void mma_tf32(float* c, const unsigned* a, const unsigned* b) {
    asm volatile(
        "mma.sync.aligned.m16n8k8.row.col.f32.tf32.tf32.f32 "
        "{%0,%1,%2,%3},{%4,%5,%6,%7},{%8,%9},{%0,%1,%2,%3};"
        : "+f"(c[0]), "+f"(c[1]), "+f"(c[2]), "+f"(c[3])
        : "r"(a[0]), "r"(a[1]), "r"(a[2]), "r"(a[3]), "r"(b[0]), "r"(b[1]));
}

#define GBM 128
#define GBN 64
#define GBK 32
#define A_STR 36
#define B_STR 72

__global__ __launch_bounds__(256)
void mma_gemm_kernel(const float* __restrict__ A, const float* __restrict__ B,
                     float* __restrict__ C, int M, int K, int Nd) {
    __shared__ float As[GBM][A_STR];
    __shared__ float Bs[GBK][B_STR];
    int tid = threadIdx.x;
    int warp = tid >> 5, lane = tid & 31;
    int wm = warp >> 1, wn = warp & 1;
    int row0 = blockIdx.y * GBM;
    int col0 = blockIdx.x * GBN;
    int g = lane >> 2, tg = lane & 3;

    float acc[2][4][4];
#pragma unroll
    for (int i = 0; i < 2; i++)
#pragma unroll
        for (int j = 0; j < 4; j++)
#pragma unroll
            for (int k = 0; k < 4; k++) acc[i][j][k] = 0.f;

    for (int k0 = 0; k0 < K; k0 += GBK) {
        // load A tile (128x32 = 1024 float4 / 256 thr = 4 each)
#pragma unroll
        for (int l = 0; l < 4; l++) {
            int lin = tid + l * 256;
            int r = lin >> 3, c4 = lin & 7;
            float4 v = make_float4(0.f, 0.f, 0.f, 0.f);
            if (row0 + r < M)
                v = *(const float4*)&A[(size_t)(row0 + r) * K + k0 + c4 * 4];
            *(float4*)&As[r][c4 * 4] = v;
        }
        // load B tile (32x64 = 512 float4 / 256 thr = 2 each)
#pragma unroll
        for (int l = 0; l < 2; l++) {
            int lin = tid + l * 256;
            int r = lin >> 4, c4 = lin & 15;
            float4 v = *(const float4*)&B[(size_t)(k0 + r) * Nd + col0 + c4 * 4];
            *(float4*)&Bs[r][c4 * 4] = v;
        }
        __syncthreads();

#pragma unroll
        for (int ks = 0; ks < 4; ks++) {
            int kb = ks * 8;
            unsigned ah[2][4], al[2][4];
#pragma unroll
            for (int mt = 0; mt < 2; mt++) {
                int r = wm * 32 + mt * 16;
                float v[4];
                v[0] = As[r + g][kb + tg];
                v[1] = As[r + g + 8][kb + tg];
                v[2] = As[r + g][kb + tg + 4];
                v[3] = As[r + g + 8][kb + tg + 4];
#pragma unroll
                for (int i = 0; i < 4; i++) {
                    unsigned hi = f2tf32(v[i]);
                    ah[mt][i] = hi;
                    al[mt][i] = f2tf32(v[i] - __uint_as_float(hi));
                }
            }
            unsigned bh[4][2], bl[4][2];
#pragma unroll
            for (int nt = 0; nt < 4; nt++) {
                int c = wn * 32 + nt * 8 + g;
                float v0 = Bs[kb + tg][c];
                float v1 = Bs[kb + tg + 4][c];
                unsigned h0 = f2tf32(v0), h1 = f2tf32(v1);
                bh[nt][0] = h0; bh[nt][1] = h1;
                bl[nt][0] = f2tf32(v0 - __uint_as_float(h0));
                bl[nt][1] = f2tf32(v1 - __uint_as_float(h1));
            }
#pragma unroll
            for (int mt = 0; mt < 2; mt++)
#pragma unroll
                for (int nt = 0; nt < 4; nt++) {
                    mma_tf32(acc[mt][nt], ah[mt], bh[nt]);
                    mma_tf32(acc[mt][nt], al[mt], bh[nt]);
                    mma_tf32(acc[mt][nt], ah[mt], bl[nt]);
                }
        }
        __syncthreads();
    }

    // store C
#pragma unroll
    for (int mt = 0; mt < 2; mt++) {
#pragma unroll
        for (int nt = 0; nt < 4; nt++) {
            int r = row0 + wm * 32 + mt * 16 + g;
            int c = col0 + wn * 32 + nt * 8 + 2 * tg;
            if (r < M) {
                C[(size_t)r * Nd + c]     = acc[mt][nt][0];
                C[(size_t)r * Nd + c + 1] = acc[mt][nt][1];
            }
            if (r + 8 < M) {
                C[(size_t)(r + 8) * Nd + c]     = acc[mt][nt][2];
                C[(size_t)(r + 8) * Nd + c + 1] = acc[mt][nt][3];
            }
        }
    }
}

// ---------------- attention coefficients ----------------
template <int HC, int H>
__global__ void attn_coef_kernel(const float* __restrict__ ht,
                                 const float* __restrict__ asrc,
                                 const float* __restrict__ adst) {
    int n = blockIdx.x;
    int t = threadIdx.x;
    float hv = ht[n * HC + t];
    float ps = hv * asrc[t];
    float pd = hv * adst[t];
#pragma unroll
    for (int o = 16; o > 0; o >>= 1) {
        ps += __shfl_down_sync(0xFFFFFFFFu, ps, o);
        pd += __shfl_down_sync(0xFFFFFFFFu, pd, o);
    }
    __shared__ float ss[HC / 32];
    __shared__ float sd[HC / 32];
    if ((t & 31) == 0) { ss[t >> 5] = ps; sd[t >> 5] = pd; }
    __syncthreads();
    if (t < H) {
        g_esrc[n * H + t] = ss[2 * t] + ss[2 * t + 1];
        g_edst[n * H + t] = sd[2 * t] + sd[2 * t + 1];
    }
}

// ---------------- fused gather softmax + aggregation ----------------
template <int H, bool RELU>
__global__ void gat_agg_kernel(const float* __restrict__ ht,
                               const float* __restrict__ bias,
                               float* __restrict__ outbuf) {
    constexpr int HC  = H * 64;
    constexpr int TPG = HC / 4;
    constexpr int NPB = 128 / TPG;
    int node = blockIdx.x * NPB + threadIdx.x / TPG;
    if (node >= N_NODES) return;
    int t = threadIdx.x % TPG;
    int head = (t * 4) >> 6;

    int beg = g_rowptr[node];
    int end = g_rowptr[node + 1];
    float ed = g_edst[node * H + head];

    float m = -INFINITY;
    for (int i = beg; i < end; i++) {
        int s = g_srclist[i];
        float e = g_esrc[s * H + head] + ed;
        e = (e > 0.f) ? e : NEG_SLOPE * e;
        m = fmaxf(m, e);
    }

    float4 acc = make_float4(0.f, 0.f, 0.f, 0.f);
    float denom = 0.f;
    const float4* htv = reinterpret_cast<const float4*>(ht);
    for (int i = beg; i < end; i++) {
        int s = g_srclist[i];
        float e = g_esrc[s * H + head] + ed;
        e = (e > 0.f) ? e : NEG_SLOPE * e;
        float ex = __expf(e - m);
        denom += ex;
        float4 hv = htv[s * TPG + t];
        acc.x = fmaf(ex, hv.x, acc.x);
        acc.y = fmaf(ex, hv.y, acc.y);
        acc.z = fmaf(ex, hv.z, acc.z);
        acc.w = fmaf(ex, hv.w, acc.w);
    }

    float inv = 1.f / (denom + 1e-16f);
    int c0 = t * 4;
    float4 r;
    r.x = acc.x * inv + bias[c0 + 0];
    r.y = acc.y * inv + bias[c0 + 1];
    r.z = acc.z * inv + bias[c0 + 2];
    r.w = acc.w * inv + bias[c0 + 3];
    if (RELU) {
        r.x = fmaxf(r.x, 0.f); r.y = fmaxf(r.y, 0.f);
        r.z = fmaxf(r.z, 0.f); r.w = fmaxf(r.w, 0.f);
    }
    reinterpret_cast<float4*>(outbuf)[node * TPG + t] = r;
}

// ---------------- pooling (batch is sorted -> run-accumulate) ----------------
// 64 threads per block, each owns channel c, processes PNB consecutive nodes.
#define PNB 128
__global__ void pool_kernel(const int* __restrict__ batch,
                            const float* __restrict__ act) {
    int c = threadIdx.x;       // 0..63
    int n0 = blockIdx.x * PNB;
    int n1 = min(n0 + PNB, N_NODES);
    int curg = batch[n0];
    float acc = 0.f;
    float cnt = 0.f;
    for (int n = n0; n < n1; n++) {
        int gidx = batch[n];
        if (gidx != curg) {
            atomicAdd(&g_pool[curg * 64 + c], acc);
            if (c == 0) atomicAdd(&g_cnt[curg], cnt);
            acc = 0.f; cnt = 0.f; curg = gidx;
        }
        acc += act[n * 64 + c];
        cnt += 1.f;
    }
    atomicAdd(&g_pool[curg * 64 + c], acc);
    if (c == 0) atomicAdd(&g_cnt[curg], cnt);
}

__global__ void finalize_kernel(const float* __restrict__ lin_w,
                                const float* __restrict__ lin_b,
                                float* __restrict__ out) {
    int g = threadIdx.x;   // 64 threads
    float cnt = fmaxf(g_cnt[g], 1.f);
    float s = 0.f;
    for (int c = 0; c < 64; c++)
        s += g_pool[g * 64 + c] * lin_w[c];
    out[g] = s / cnt + lin_b[0];
}

// ---------------- launch ----------------
extern "C" void kernel_launch(void* const* d_in, const int* in_sizes, int n_in,
                              void* d_out, int out_size) {
    (void)in_sizes; (void)n_in; (void)out_size;
    const float* x      = (const float*)d_in[0];
    const int*   ei     = (const int*)  d_in[1];
    const int*   batch  = (const int*)  d_in[2];
    const float* W0     = (const float*)d_in[3];
    const float* asrc0  = (const float*)d_in[4];
    const float* adst0  = (const float*)d_in[5];
    const float* b0     = (const float*)d_in[6];
    const float* W1     = (const float*)d_in[7];
    const float* asrc1  = (const float*)d_in[8];
    const float* adst1  = (const float*)d_in[9];
    const float* b1     = (const float*)d_in[10];
    const float* W2     = (const float*)d_in[11];
    const float* asrc2  = (const float*)d_in[12];
    const float* adst2  = (const float*)d_in[13];
    const float* b2     = (const float*)d_in[14];
    const float* lin_w  = (const float*)d_in[15];
    const float* lin_b  = (const float*)d_in[16];
    float* out = (float*)d_out;

    void *p_ht_v, *p_act_v, *p_deg_v, *p_pool_v, *p_cnt_v;
    cudaGetSymbolAddress(&p_ht_v, g_ht);
    cudaGetSymbolAddress(&p_act_v, g_act);
    cudaGetSymbolAddress(&p_deg_v, g_deg);
    cudaGetSymbolAddress(&p_pool_v, g_pool);
    cudaGetSymbolAddress(&p_cnt_v, g_cnt);
    float* p_ht  = (float*)p_ht_v;
    float* p_act = (float*)p_act_v;

    cudaMemsetAsync(p_deg_v, 0, N_NODES * sizeof(int));
    cudaMemsetAsync(p_pool_v, 0, NGRAPH * 64 * sizeof(float));
    cudaMemsetAsync(p_cnt_v, 0, NGRAPH * sizeof(float));

    count_deg_kernel<<<(ET + 255) / 256, 256>>>(ei);
    scan_kernel<<<1, 1024>>>();
    fill_csr_kernel<<<(ET + 255) / 256, 256>>>(ei);

    // ----- layer 0: 128 -> 256 -----
    {
        dim3 grid(256 / GBN, (N_NODES + GBM - 1) / GBM);
        mma_gemm_kernel<<<grid, 256>>>(x, W0, p_ht, N_NODES, 128, 256);
        attn_coef_kernel<256, 4><<<N_NODES, 256>>>(p_ht, asrc0, adst0);
        gat_agg_kernel<4, true><<<(N_NODES + 1) / 2, 128>>>(p_ht, b0, p_act);
    }
    // ----- layer 1: 256 -> 256 -----
    {
        dim3 grid(256 / GBN, (N_NODES + GBM - 1) / GBM);
        mma_gemm_kernel<<<grid, 256>>>(p_act, W1, p_ht, N_NODES, 256, 256);
        attn_coef_kernel<256, 4><<<N_NODES, 256>>>(p_ht, asrc1, adst1);
        gat_agg_kernel<4, true><<<(N_NODES + 1) / 2, 128>>>(p_ht, b1, p_act);
    }
    // ----- layer 2: 256 -> 64 -----
    {
        dim3 grid(64 / GBN, (N_NODES + GBM - 1) / GBM);
        mma_gemm_kernel<<<grid, 256>>>(p_act, W2, p_ht, N_NODES, 256, 64);
        attn_coef_kernel<64, 1><<<N_NODES, 64>>>(p_ht, asrc2, adst2);
        gat_agg_kernel<1, false><<<(N_NODES + 7) / 8, 128>>>(p_ht, b2, p_act);
    }
    // ----- global mean pool + linear -----
    pool_kernel<<<(N_NODES + PNB - 1) / PNB, 64>>>(batch, p_act);
    finalize_kernel<<<1, 64>>>(lin_w, lin_b, out);
}

// round 3
// speedup vs baseline: 1.5858x; 1.3889x over previous
#include <cuda_runtime.h>
#include <cuda_fp16.h>
#include <cuda_bf16.h>
#include <math.h>

// ---------------- problem constants ----------------
#define N_NODES 50000
#define E_EDGES 800000
#define ET (E_EDGES + N_NODES)   // edges + self loops = 850000
#define NGRAPH 64
#define NEG_SLOPE 0.2f
#define NBLK_SCAN 196            // ceil(50000/256)

// ---------------- device scratch ----------------
__device__ float  g_ht [N_NODES * 256];   // GEMM output fp32
__device__ __half g_hth[N_NODES * 256];   // fp16 copy for agg gather
__device__ float  g_act[N_NODES * 256];   // layer activation
__device__ float  g_esrc[N_NODES * 4];
__device__ float  g_edst[N_NODES * 4];
__device__ int    g_deg   [N_NODES];
__device__ int    g_rowptr[N_NODES + 1];
__device__ int    g_cursor[N_NODES];
__device__ int    g_srclist[ET];
__device__ int    g_bsum[256];
__device__ int    g_boff[256];
__device__ float  g_pool[NGRAPH * 64];
__device__ float  g_cnt [NGRAPH];

// ---------------- CSR build (by destination) ----------------
__global__ void count_deg_kernel(const int* __restrict__ ei) {
    int e = blockIdx.x * blockDim.x + threadIdx.x;
    if (e >= ET) return;
    int d = (e < E_EDGES) ? ei[E_EDGES + e] : (e - E_EDGES);
    atomicAdd(&g_deg[d], 1);
}

__global__ void deg_blocksum_kernel() {           // grid=NBLK_SCAN, block=256
    __shared__ int sm[256];
    int idx = blockIdx.x * 256 + threadIdx.x;
    sm[threadIdx.x] = (idx < N_NODES) ? g_deg[idx] : 0;
    __syncthreads();
    for (int o = 128; o > 0; o >>= 1) {
        if (threadIdx.x < o) sm[threadIdx.x] += sm[threadIdx.x + o];
        __syncthreads();
    }
    if (threadIdx.x == 0) g_bsum[blockIdx.x] = sm[0];
}

__global__ void bsum_scan_kernel() {              // 1 block, 256 threads
    __shared__ int sm[256];
    int t = threadIdx.x;
    sm[t] = (t < NBLK_SCAN) ? g_bsum[t] : 0;
    __syncthreads();
    for (int o = 1; o < 256; o <<= 1) {
        int v = (t >= o) ? sm[t - o] : 0;
        __syncthreads();
        sm[t] += v;
        __syncthreads();
    }
    g_boff[t] = (t == 0) ? 0 : sm[t - 1];
    if (t == NBLK_SCAN - 1) g_rowptr[N_NODES] = sm[t];
}

__global__ void rowptr_fill_kernel() {            // grid=NBLK_SCAN, block=256
    __shared__ int sm[256];
    int t = threadIdx.x;
    int idx = blockIdx.x * 256 + t;
    int v = (idx < N_NODES) ? g_deg[idx] : 0;
    sm[t] = v;
    __syncthreads();
    for (int o = 1; o < 256; o <<= 1) {
        int u = (t >= o) ? sm[t - o] : 0;
        __syncthreads();
        sm[t] += u;
        __syncthreads();
    }
    if (idx < N_NODES) {
        int excl = g_boff[blockIdx.x] + sm[t] - v;
        g_rowptr[idx] = excl;
        g_cursor[idx] = excl;
    }
}

__global__ void fill_csr_kernel(const int* __restrict__ ei) {
    int e = blockIdx.x * blockDim.x + threadIdx.x;
    if (e >= ET) return;
    int s, d;
    if (e < E_EDGES) { s = ei[e]; d = ei[E_EDGES + e]; }
    else             { s = e - E_EDGES; d = s; }
    int pos = atomicAdd(&g_cursor[d], 1);
    g_srclist[pos] = s;
}

// ---------------- 3xTF32 tensor-core GEMM, double-buffered ----------------
__device__ __forceinline__ unsigned f2tf32(float f) {
    unsigned r;
    asm("cvt.rna.tf32.f32 %0, %1;" : "=r"(r) : "f"(f));
    return r;
}

__device__ __forceinline__ void mma_tf32(float* c, const unsigned* a, const unsigned* b) {
    asm volatile(
        "mma.sync.aligned.m16n8k8.row.col.f32.tf32.tf32.f32 "
        "{%0,%1,%2,%3},{%4,%5,%6,%7},{%8,%9},{%0,%1,%2,%3};"
        : "+f"(c[0]), "+f"(c[1]), "+f"(c[2]), "+f"(c[3])
        : "r"(a[0]), "r"(a[1]), "r"(a[2]), "r"(a[3]), "r"(b[0]), "r"(b[1]));
}

#define GBM 128
#define GBN 64
#define GBK 32
#define A_STR 36
#define B_STR 72
#define GEMM_SMEM (2*GBM*A_STR*4 + 2*2*GBK*B_STR*4)   // 73728 bytes

__global__ __launch_bounds__(256, 2)
void mma_gemm_kernel(const float* __restrict__ A, const float* __restrict__ B,
                     float* __restrict__ C, int M, int K, int Nd) {
    extern __shared__ char sraw[];
    float*    As = (float*)sraw;                          // [2][128*36]
    unsigned* Bh = (unsigned*)(sraw + 2*GBM*A_STR*4);     // [2][32*72]
    unsigned* Bl = Bh + 2*GBK*B_STR;

    const int tid  = threadIdx.x;
    const int warp = tid >> 5, lane = tid & 31;
    const int wm = warp >> 1, wn = warp & 1;
    const int row0 = blockIdx.y * GBM, col0 = blockIdx.x * GBN;
    const int g = lane >> 2, tg = lane & 3;
    const int arr = tid >> 3, ac = (tid & 7) * 4;
    const int brr = tid >> 4, bc = (tid & 15) * 4;

    float acc[2][4][4] = {};
    float4 a_pre[4];
    float4 b_pre[2];

    auto ldg = [&](int k0) {
#pragma unroll
        for (int l = 0; l < 4; l++) {
            int r = arr + l * 32;
            a_pre[l] = (row0 + r < M)
                ? *(const float4*)&A[(size_t)(row0 + r) * K + k0 + ac]
                : make_float4(0.f, 0.f, 0.f, 0.f);
        }
#pragma unroll
        for (int l = 0; l < 2; l++) {
            int r = brr + l * 16;
            b_pre[l] = *(const float4*)&B[(size_t)(k0 + r) * Nd + col0 + bc];
        }
    };
    auto sts = [&](int s) {
        float* as = As + s * GBM * A_STR;
#pragma unroll
        for (int l = 0; l < 4; l++)
            *(float4*)&as[(arr + l * 32) * A_STR + ac] = a_pre[l];
        unsigned* bh = Bh + s * GBK * B_STR;
        unsigned* bl = Bl + s * GBK * B_STR;
#pragma unroll
        for (int l = 0; l < 2; l++) {
            float vv[4] = {b_pre[l].x, b_pre[l].y, b_pre[l].z, b_pre[l].w};
            uint4 uh, ul;
            unsigned* uhp = &uh.x;
            unsigned* ulp = &ul.x;
#pragma unroll
            for (int k = 0; k < 4; k++) {
                unsigned hi = f2tf32(vv[k]);
                uhp[k] = hi;
                ulp[k] = f2tf32(vv[k] - __uint_as_float(hi));
            }
            int off = (brr + l * 16) * B_STR + bc;
            *(uint4*)&bh[off] = uh;
            *(uint4*)&bl[off] = ul;
        }
    };
    auto compute = [&](int s) {
        const float*    as = As + s * GBM * A_STR;
        const unsigned* bh = Bh + s * GBK * B_STR;
        const unsigned* bl = Bl + s * GBK * B_STR;
#pragma unroll
        for (int ks = 0; ks < 4; ks++) {
            int kb = ks * 8;
            unsigned ah[2][4], alr[2][4];
#pragma unroll
            for (int mt = 0; mt < 2; mt++) {
                int r = wm * 32 + mt * 16;
                float v[4];
                v[0] = as[(r + g) * A_STR + kb + tg];
                v[1] = as[(r + g + 8) * A_STR + kb + tg];
                v[2] = as[(r + g) * A_STR + kb + tg + 4];
                v[3] = as[(r + g + 8) * A_STR + kb + tg + 4];
#pragma unroll
                for (int i = 0; i < 4; i++) {
                    unsigned hi = f2tf32(v[i]);
                    ah[mt][i]  = hi;
                    alr[mt][i] = f2tf32(v[i] - __uint_as_float(hi));
                }
            }
            unsigned bhf[4][2], blf[4][2];
#pragma unroll
            for (int nt = 0; nt < 4; nt++) {
                int c = wn * 32 + nt * 8 + g;
                bhf[nt][0] = bh[(kb + tg) * B_STR + c];
                bhf[nt][1] = bh[(kb + tg + 4) * B_STR + c];
                blf[nt][0] = bl[(kb + tg) * B_STR + c];
                blf[nt][1] = bl[(kb + tg + 4) * B_STR + c];
            }
#pragma unroll
            for (int mt = 0; mt < 2; mt++)
#pragma unroll
                for (int nt = 0; nt < 4; nt++) {
                    mma_tf32(acc[mt][nt], ah[mt],  bhf[nt]);
                    mma_tf32(acc[mt][nt], alr[mt], bhf[nt]);
                    mma_tf32(acc[mt][nt], ah[mt],  blf[nt]);
                }
        }
    };

    ldg(0); sts(0); __syncthreads();
    int nk = K / GBK;
    for (int i = 0; i < nk; i++) {
        if (i + 1 < nk) ldg((i + 1) * GBK);
        compute(i & 1);
        if (i + 1 < nk) sts((i + 1) & 1);
        __syncthreads();
    }

#pragma unroll
    for (int mt = 0; mt < 2; mt++)
#pragma unroll
        for (int nt = 0; nt < 4; nt++) {
            int r = row0 + wm * 32 + mt * 16 + g;
            int c = col0 + wn * 32 + nt * 8 + 2 * tg;
            if (r < M)
                *(float2*)&C[(size_t)r * Nd + c] = make_float2(acc[mt][nt][0], acc[mt][nt][1]);
            if (r + 8 < M)
                *(float2*)&C[(size_t)(r + 8) * Nd + c] = make_float2(acc[mt][nt][2], acc[mt][nt][3]);
        }
}

// ---------------- attention coefficients + fp16 conversion ----------------
template <int HC, int H>
__global__ void attn_coef_kernel(const float* __restrict__ ht,
                                 const float* __restrict__ asrc,
                                 const float* __restrict__ adst) {
    int n = blockIdx.x;
    int t = threadIdx.x;
    float hv = ht[n * HC + t];
    g_hth[n * HC + t] = __float2half(hv);
    float ps = hv * asrc[t];
    float pd = hv * adst[t];
#pragma unroll
    for (int o = 16; o > 0; o >>= 1) {
        ps += __shfl_down_sync(0xFFFFFFFFu, ps, o);
        pd += __shfl_down_sync(0xFFFFFFFFu, pd, o);
    }
    __shared__ float ss[HC / 32];
    __shared__ float sd[HC / 32];
    if ((t & 31) == 0) { ss[t >> 5] = ps; sd[t >> 5] = pd; }
    __syncthreads();
    if (t < H) {
        g_esrc[n * H + t] = ss[2 * t] + ss[2 * t + 1];
        g_edst[n * H + t] = sd[2 * t] + sd[2 * t + 1];
    }
}

// ---------------- fused gather softmax + aggregation (fp16 gather) ----------------
template <int H, bool RELU>
__global__ void gat_agg_kernel(const float* __restrict__ bias,
                               float* __restrict__ outbuf) {
    constexpr int HC  = H * 64;
    constexpr int TPG = HC / 8;        // thread handles 8 halves (16 B)
    constexpr int NPB = 128 / TPG;
    int node = blockIdx.x * NPB + threadIdx.x / TPG;
    if (node >= N_NODES) return;
    int t = threadIdx.x % TPG;
    int head = (H == 1) ? 0 : (t >> 3);

    int beg = g_rowptr[node];
    int end = g_rowptr[node + 1];
    float ed = g_edst[node * H + head];

    float m = -INFINITY;
    for (int i = beg; i < end; i++) {
        int s = g_srclist[i];
        float e = g_esrc[s * H + head] + ed;
        e = (e > 0.f) ? e : NEG_SLOPE * e;
        m = fmaxf(m, e);
    }

    float acc[8] = {};
    float denom = 0.f;
    const uint4* hv4 = reinterpret_cast<const uint4*>(g_hth);
    for (int i = beg; i < end; i++) {
        int s = g_srclist[i];
        float e = g_esrc[s * H + head] + ed;
        e = (e > 0.f) ? e : NEG_SLOPE * e;
        float ex = __expf(e - m);
        denom += ex;
        uint4 u = hv4[(size_t)s * TPG + t];
        unsigned uu[4] = {u.x, u.y, u.z, u.w};
#pragma unroll
        for (int k = 0; k < 4; k++) {
            __half2 h2 = *reinterpret_cast<__half2*>(&uu[k]);
            float2 f = __half22float2(h2);
            acc[2 * k]     = fmaf(ex, f.x, acc[2 * k]);
            acc[2 * k + 1] = fmaf(ex, f.y, acc[2 * k + 1]);
        }
    }

    float inv = 1.f / (denom + 1e-16f);
    int c0 = t * 8;
    float o[8];
#pragma unroll
    for (int k = 0; k < 8; k++) {
        float v = acc[k] * inv + bias[c0 + k];
        o[k] = RELU ? fmaxf(v, 0.f) : v;
    }
    float4* ob = reinterpret_cast<float4*>(&outbuf[(size_t)node * HC + c0]);
    ob[0] = make_float4(o[0], o[1], o[2], o[3]);
    ob[1] = make_float4(o[4], o[5], o[6], o[7]);
}

// ---------------- pooling (batch sorted -> run-accumulate) ----------------
#define PNB 128
__global__ void pool_kernel(const int* __restrict__ batch,
                            const float* __restrict__ act) {
    int c = threadIdx.x;       // 0..63
    int n0 = blockIdx.x * PNB;
    int n1 = min(n0 + PNB, N_NODES);
    int curg = batch[n0];
    float acc = 0.f, cnt = 0.f;
    for (int n = n0; n < n1; n++) {
        int gidx = batch[n];
        if (gidx != curg) {
            atomicAdd(&g_pool[curg * 64 + c], acc);
            if (c == 0) atomicAdd(&g_cnt[curg], cnt);
            acc = 0.f; cnt = 0.f; curg = gidx;
        }
        acc += act[n * 64 + c];
        cnt += 1.f;
    }
    atomicAdd(&g_pool[curg * 64 + c], acc);
    if (c == 0) atomicAdd(&g_cnt[curg], cnt);
}

__global__ void finalize_kernel(const float* __restrict__ lin_w,
                                const float* __restrict__ lin_b,
                                float* __restrict__ out) {
    int g = threadIdx.x;   // 64 threads
    float cnt = fmaxf(g_cnt[g], 1.f);
    float s = 0.f;
    for (int c = 0; c < 64; c++)
        s += g_pool[g * 64 + c] * lin_w[c];
    out[g] = s / cnt + lin_b[0];
}

// ---------------- launch ----------------
extern "C" void kernel_launch(void* const* d_in, const int* in_sizes, int n_in,
                              void* d_out, int out_size) {
    (void)in_sizes; (void)n_in; (void)out_size;
    const float* x      = (const float*)d_in[0];
    const int*   ei     = (const int*)  d_in[1];
    const int*   batch  = (const int*)  d_in[2];
    const float* W0     = (const float*)d_in[3];
    const float* asrc0  = (const float*)d_in[4];
    const float* adst0  = (const float*)d_in[5];
    const float* b0     = (const float*)d_in[6];
    const float* W1     = (const float*)d_in[7];
    const float* asrc1  = (const float*)d_in[8];
    const float* adst1  = (const float*)d_in[9];
    const float* b1     = (const float*)d_in[10];
    const float* W2     = (const float*)d_in[11];
    const float* asrc2  = (const float*)d_in[12];
    const float* adst2  = (const float*)d_in[13];
    const float* b2     = (const float*)d_in[14];
    const float* lin_w  = (const float*)d_in[15];
    const float* lin_b  = (const float*)d_in[16];
    float* out = (float*)d_out;

    void *p_ht_v, *p_act_v, *p_deg_v, *p_pool_v, *p_cnt_v;
    cudaGetSymbolAddress(&p_ht_v, g_ht);
    cudaGetSymbolAddress(&p_act_v, g_act);
    cudaGetSymbolAddress(&p_deg_v, g_deg);
    cudaGetSymbolAddress(&p_pool_v, g_pool);
    cudaGetSymbolAddress(&p_cnt_v, g_cnt);
    float* p_ht  = (float*)p_ht_v;
    float* p_act = (float*)p_act_v;

    cudaFuncSetAttribute(mma_gemm_kernel, cudaFuncAttributeMaxDynamicSharedMemorySize, GEMM_SMEM);

    cudaMemsetAsync(p_deg_v, 0, N_NODES * sizeof(int));
    cudaMemsetAsync(p_pool_v, 0, NGRAPH * 64 * sizeof(float));
    cudaMemsetAsync(p_cnt_v, 0, NGRAPH * sizeof(float));

    count_deg_kernel<<<(ET + 255) / 256, 256>>>(ei);
    deg_blocksum_kernel<<<NBLK_SCAN, 256>>>();
    bsum_scan_kernel<<<1, 256>>>();
    rowptr_fill_kernel<<<NBLK_SCAN, 256>>>();
    fill_csr_kernel<<<(ET + 255) / 256, 256>>>(ei);

    // ----- layer 0: 128 -> 256 -----
    {
        dim3 grid(256 / GBN, (N_NODES + GBM - 1) / GBM);
        mma_gemm_kernel<<<grid, 256, GEMM_SMEM>>>(x, W0, p_ht, N_NODES, 128, 256);
        attn_coef_kernel<256, 4><<<N_NODES, 256>>>(p_ht, asrc0, adst0);
        gat_agg_kernel<4, true><<<(N_NODES + 3) / 4, 128>>>(b0, p_act);
    }
    // ----- layer 1: 256 -> 256 -----
    {
        dim3 grid(256 / GBN, (N_NODES + GBM - 1) / GBM);
        mma_gemm_kernel<<<grid, 256, GEMM_SMEM>>>(p_act, W1, p_ht, N_NODES, 256, 256);
        attn_coef_kernel<256, 4><<<N_NODES, 256>>>(p_ht, asrc1, adst1);
        gat_agg_kernel<4, true><<<(N_NODES + 3) / 4, 128>>>(b1, p_act);
    }
    // ----- layer 2: 256 -> 64 -----
    {
        dim3 grid(64 / GBN, (N_NODES + GBM - 1) / GBM);
        mma_gemm_kernel<<<grid, 256, GEMM_SMEM>>>(p_act, W2, p_ht, N_NODES, 256, 64);
        attn_coef_kernel<64, 1><<<N_NODES, 64>>>(p_ht, asrc2, adst2);
        gat_agg_kernel<1, false><<<(N_NODES + 15) / 16, 128>>>(b2, p_act);
    }
    // ----- global mean pool + linear -----
    pool_kernel<<<(N_NODES + PNB - 1) / PNB, 64>>>(batch, p_act);
    finalize_kernel<<<1, 64>>>(lin_w, lin_b, out);
}

// round 4
// speedup vs baseline: 2.0210x; 1.2745x over previous
#include <cuda_runtime.h>
#include <cuda_fp16.h>
#include <cuda_bf16.h>
#include <math.h>

// ---------------- problem constants ----------------
#define N_NODES 50000
#define E_EDGES 800000
#define ET (E_EDGES + N_NODES)   // edges + self loops = 850000
#define NGRAPH 64
#define NEG_SLOPE 0.2f
#define NBLK_SCAN 196            // ceil(50000/256)

// ---------------- device scratch ----------------
__device__ __half g_hth[N_NODES * 256];   // fp16 features for agg gather
__device__ float  g_act[N_NODES * 256];   // layer activation (agg output, GEMM input)
__device__ float  g_esrc[N_NODES * 4];
__device__ float  g_edst[N_NODES * 4];
__device__ int    g_deg   [N_NODES];
__device__ int    g_rowptr[N_NODES + 1];
__device__ int    g_cursor[N_NODES];
__device__ int    g_srclist[ET];
__device__ int    g_bsum[256];
__device__ int    g_boff[256];
__device__ float  g_pool[NGRAPH * 64];
__device__ float  g_cnt [NGRAPH];

// ---------------- CSR build (by destination) ----------------
__global__ void count_deg_kernel(const int* __restrict__ ei) {
    int e = blockIdx.x * blockDim.x + threadIdx.x;
    if (e >= ET) return;
    int d = (e < E_EDGES) ? ei[E_EDGES + e] : (e - E_EDGES);
    atomicAdd(&g_deg[d], 1);
}

__global__ void deg_blocksum_kernel() {
    __shared__ int sm[256];
    int idx = blockIdx.x * 256 + threadIdx.x;
    sm[threadIdx.x] = (idx < N_NODES) ? g_deg[idx] : 0;
    __syncthreads();
    for (int o = 128; o > 0; o >>= 1) {
        if (threadIdx.x < o) sm[threadIdx.x] += sm[threadIdx.x + o];
        __syncthreads();
    }
    if (threadIdx.x == 0) g_bsum[blockIdx.x] = sm[0];
}

__global__ void bsum_scan_kernel() {
    __shared__ int sm[256];
    int t = threadIdx.x;
    sm[t] = (t < NBLK_SCAN) ? g_bsum[t] : 0;
    __syncthreads();
    for (int o = 1; o < 256; o <<= 1) {
        int v = (t >= o) ? sm[t - o] : 0;
        __syncthreads();
        sm[t] += v;
        __syncthreads();
    }
    g_boff[t] = (t == 0) ? 0 : sm[t - 1];
    if (t == NBLK_SCAN - 1) g_rowptr[N_NODES] = sm[t];
}

__global__ void rowptr_fill_kernel() {
    __shared__ int sm[256];
    int t = threadIdx.x;
    int idx = blockIdx.x * 256 + t;
    int v = (idx < N_NODES) ? g_deg[idx] : 0;
    sm[t] = v;
    __syncthreads();
    for (int o = 1; o < 256; o <<= 1) {
        int u = (t >= o) ? sm[t - o] : 0;
        __syncthreads();
        sm[t] += u;
        __syncthreads();
    }
    if (idx < N_NODES) {
        int excl = g_boff[blockIdx.x] + sm[t] - v;
        g_rowptr[idx] = excl;
        g_cursor[idx] = excl;
    }
}

__global__ void fill_csr_kernel(const int* __restrict__ ei) {
    int e = blockIdx.x * blockDim.x + threadIdx.x;
    if (e >= ET) return;
    int s, d;
    if (e < E_EDGES) { s = ei[e]; d = ei[E_EDGES + e]; }
    else             { s = e - E_EDGES; d = s; }
    int pos = atomicAdd(&g_cursor[d], 1);
    g_srclist[pos] = s;
}

// ---------------- 3xTF32 GEMM + fused attention-coefficient epilogue ----------------
__device__ __forceinline__ unsigned f2tf32(float f) {
    unsigned r;
    asm("cvt.rna.tf32.f32 %0, %1;" : "=r"(r) : "f"(f));
    return r;
}

__device__ __forceinline__ void mma_tf32(float* c, const unsigned* a, const unsigned* b) {
    asm volatile(
        "mma.sync.aligned.m16n8k8.row.col.f32.tf32.tf32.f32 "
        "{%0,%1,%2,%3},{%4,%5,%6,%7},{%8,%9},{%0,%1,%2,%3};"
        : "+f"(c[0]), "+f"(c[1]), "+f"(c[2]), "+f"(c[3])
        : "r"(a[0]), "r"(a[1]), "r"(a[2]), "r"(a[3]), "r"(b[0]), "r"(b[1]));
}

#define GBM 128
#define GBN 64
#define GBK 32
#define A_STR 36
#define B_STR 72
#define GEMM_SMEM (2*GBM*A_STR*4 + 2*2*GBK*B_STR*4)   // 73728 bytes

// Output: fp16 h -> g_hth, per-(row,head) e_src/e_dst -> g_esrc/g_edst.
// grid.x = Nd/64 = heads; each block covers one head's 64 channels.
__global__ __launch_bounds__(256, 2)
void mma_gemm_attn_kernel(const float* __restrict__ A, const float* __restrict__ B,
                          const float* __restrict__ asrc, const float* __restrict__ adst,
                          int M, int K, int Nd, int H) {
    extern __shared__ char sraw[];
    float*    As = (float*)sraw;                          // [2][128*36]
    unsigned* Bh = (unsigned*)(sraw + 2*GBM*A_STR*4);     // [2][32*72]
    unsigned* Bl = Bh + 2*GBK*B_STR;

    const int tid  = threadIdx.x;
    const int warp = tid >> 5, lane = tid & 31;
    const int wm = warp >> 1, wn = warp & 1;
    const int row0 = blockIdx.y * GBM, col0 = blockIdx.x * GBN;
    const int head = blockIdx.x;
    const int g = lane >> 2, tg = lane & 3;
    const int arr = tid >> 3, ac = (tid & 7) * 4;
    const int brr = tid >> 4, bc = (tid & 15) * 4;

    float acc[2][4][4] = {};
    float4 a_pre[4];
    float4 b_pre[2];

    auto ldg = [&](int k0) {
#pragma unroll
        for (int l = 0; l < 4; l++) {
            int r = arr + l * 32;
            a_pre[l] = (row0 + r < M)
                ? *(const float4*)&A[(size_t)(row0 + r) * K + k0 + ac]
                : make_float4(0.f, 0.f, 0.f, 0.f);
        }
#pragma unroll
        for (int l = 0; l < 2; l++) {
            int r = brr + l * 16;
            b_pre[l] = *(const float4*)&B[(size_t)(k0 + r) * Nd + col0 + bc];
        }
    };
    auto sts = [&](int s) {
        float* as = As + s * GBM * A_STR;
#pragma unroll
        for (int l = 0; l < 4; l++)
            *(float4*)&as[(arr + l * 32) * A_STR + ac] = a_pre[l];
        unsigned* bh = Bh + s * GBK * B_STR;
        unsigned* bl = Bl + s * GBK * B_STR;
#pragma unroll
        for (int l = 0; l < 2; l++) {
            float vv[4] = {b_pre[l].x, b_pre[l].y, b_pre[l].z, b_pre[l].w};
            uint4 uh, ul;
            unsigned* uhp = &uh.x;
            unsigned* ulp = &ul.x;
#pragma unroll
            for (int k = 0; k < 4; k++) {
                unsigned hi = f2tf32(vv[k]);
                uhp[k] = hi;
                ulp[k] = f2tf32(vv[k] - __uint_as_float(hi));
            }
            int off = (brr + l * 16) * B_STR + bc;
            *(uint4*)&bh[off] = uh;
            *(uint4*)&bl[off] = ul;
        }
    };
    auto compute = [&](int s) {
        const float*    as = As + s * GBM * A_STR;
        const unsigned* bh = Bh + s * GBK * B_STR;
        const unsigned* bl = Bl + s * GBK * B_STR;
#pragma unroll
        for (int ks = 0; ks < 4; ks++) {
            int kb = ks * 8;
            unsigned ah[2][4], alr[2][4];
#pragma unroll
            for (int mt = 0; mt < 2; mt++) {
                int r = wm * 32 + mt * 16;
                float v[4];
                v[0] = as[(r + g) * A_STR + kb + tg];
                v[1] = as[(r + g + 8) * A_STR + kb + tg];
                v[2] = as[(r + g) * A_STR + kb + tg + 4];
                v[3] = as[(r + g + 8) * A_STR + kb + tg + 4];
#pragma unroll
                for (int i = 0; i < 4; i++) {
                    unsigned hi = f2tf32(v[i]);
                    ah[mt][i]  = hi;
                    alr[mt][i] = f2tf32(v[i] - __uint_as_float(hi));
                }
            }
            unsigned bhf[4][2], blf[4][2];
#pragma unroll
            for (int nt = 0; nt < 4; nt++) {
                int c = wn * 32 + nt * 8 + g;
                bhf[nt][0] = bh[(kb + tg) * B_STR + c];
                bhf[nt][1] = bh[(kb + tg + 4) * B_STR + c];
                blf[nt][0] = bl[(kb + tg) * B_STR + c];
                blf[nt][1] = bl[(kb + tg + 4) * B_STR + c];
            }
#pragma unroll
            for (int mt = 0; mt < 2; mt++)
#pragma unroll
                for (int nt = 0; nt < 4; nt++) {
                    mma_tf32(acc[mt][nt], ah[mt],  bhf[nt]);
                    mma_tf32(acc[mt][nt], alr[mt], bhf[nt]);
                    mma_tf32(acc[mt][nt], ah[mt],  blf[nt]);
                }
        }
    };

    ldg(0); sts(0); __syncthreads();
    int nk = K / GBK;
    for (int i = 0; i < nk; i++) {
        if (i + 1 < nk) ldg((i + 1) * GBK);
        compute(i & 1);
        if (i + 1 < nk) sts((i + 1) & 1);
        __syncthreads();
    }

    // ---- epilogue 1: fp16 feature store ----
#pragma unroll
    for (int mt = 0; mt < 2; mt++)
#pragma unroll
        for (int nt = 0; nt < 4; nt++) {
            int r = row0 + wm * 32 + mt * 16 + g;
            int c = col0 + wn * 32 + nt * 8 + 2 * tg;
            if (r < M)
                *(__half2*)&g_hth[(size_t)r * Nd + c] =
                    __floats2half2_rn(acc[mt][nt][0], acc[mt][nt][1]);
            if (r + 8 < M)
                *(__half2*)&g_hth[(size_t)(r + 8) * Nd + c] =
                    __floats2half2_rn(acc[mt][nt][2], acc[mt][nt][3]);
        }

    // ---- epilogue 2: attention coefficients ----
    // per-thread partial dot over its 8 columns, for its 4 rows
    float ps[2][2] = {}, pd[2][2] = {};
    const int hb = head * 64;
#pragma unroll
    for (int nt = 0; nt < 4; nt++) {
        int cl = wn * 32 + nt * 8 + 2 * tg;
        float as0 = asrc[hb + cl], as1 = asrc[hb + cl + 1];
        float ad0 = adst[hb + cl], ad1 = adst[hb + cl + 1];
#pragma unroll
        for (int mt = 0; mt < 2; mt++) {
            ps[mt][0] += acc[mt][nt][0] * as0 + acc[mt][nt][1] * as1;
            ps[mt][1] += acc[mt][nt][2] * as0 + acc[mt][nt][3] * as1;
            pd[mt][0] += acc[mt][nt][0] * ad0 + acc[mt][nt][1] * ad1;
            pd[mt][1] += acc[mt][nt][2] * ad0 + acc[mt][nt][3] * ad1;
        }
    }
    // reduce over tg group (lanes xor 1, xor 2)
#pragma unroll
    for (int o = 1; o < 4; o <<= 1) {
#pragma unroll
        for (int mt = 0; mt < 2; mt++)
#pragma unroll
            for (int rr = 0; rr < 2; rr++) {
                ps[mt][rr] += __shfl_xor_sync(0xFFFFFFFFu, ps[mt][rr], o);
                pd[mt][rr] += __shfl_xor_sync(0xFFFFFFFFu, pd[mt][rr], o);
            }
    }
    float* sm_src = (float*)sraw;          // [2][128]
    float* sm_dst = sm_src + 2 * GBM;      // [2][128]
    __syncthreads();                        // compute loop done reading smem
    if (tg == 0) {
#pragma unroll
        for (int mt = 0; mt < 2; mt++)
#pragma unroll
            for (int rr = 0; rr < 2; rr++) {
                int rl = wm * 32 + mt * 16 + g + rr * 8;
                sm_src[wn * GBM + rl] = ps[mt][rr];
                sm_dst[wn * GBM + rl] = pd[mt][rr];
            }
    }
    __syncthreads();
    if (tid < GBM) {
        int r = row0 + tid;
        if (r < M) {
            g_esrc[(size_t)r * H + head] = sm_src[tid] + sm_src[GBM + tid];
            g_edst[(size_t)r * H + head] = sm_dst[tid] + sm_dst[GBM + tid];
        }
    }
}

// ---------------- fused gather softmax + aggregation (single pass, fp16 gather) ----------------
template <int H, bool RELU>
__global__ void gat_agg_kernel(const float* __restrict__ bias,
                               float* __restrict__ outbuf) {
    constexpr int HC  = H * 64;
    constexpr int TPG = HC / 8;        // thread handles 8 halves (16 B)
    constexpr int NPB = 128 / TPG;
    int node = blockIdx.x * NPB + threadIdx.x / TPG;
    if (node >= N_NODES) return;
    int t = threadIdx.x % TPG;
    int head = (H == 1) ? 0 : (t >> 3);

    int beg = g_rowptr[node];
    int end = g_rowptr[node + 1];
    float ed = g_edst[node * H + head];

    float acc[8] = {};
    float denom = 0.f;
    const uint4* hv4 = reinterpret_cast<const uint4*>(g_hth);
    for (int i = beg; i < end; i++) {
        int s = g_srclist[i];
        float e = g_esrc[s * H + head] + ed;
        e = (e > 0.f) ? e : NEG_SLOPE * e;
        float ex = __expf(e);          // max-shift cancels in alpha; |e| is small
        denom += ex;
        uint4 u = hv4[(size_t)s * TPG + t];
        unsigned uu[4] = {u.x, u.y, u.z, u.w};
#pragma unroll
        for (int k = 0; k < 4; k++) {
            __half2 h2 = *reinterpret_cast<__half2*>(&uu[k]);
            float2 f = __half22float2(h2);
            acc[2 * k]     = fmaf(ex, f.x, acc[2 * k]);
            acc[2 * k + 1] = fmaf(ex, f.y, acc[2 * k + 1]);
        }
    }

    float inv = 1.f / (denom + 1e-16f);
    int c0 = t * 8;
    float o[8];
#pragma unroll
    for (int k = 0; k < 8; k++) {
        float v = acc[k] * inv + bias[c0 + k];
        o[k] = RELU ? fmaxf(v, 0.f) : v;
    }
    float4* ob = reinterpret_cast<float4*>(&outbuf[(size_t)node * HC + c0]);
    ob[0] = make_float4(o[0], o[1], o[2], o[3]);
    ob[1] = make_float4(o[4], o[5], o[6], o[7]);
}

// ---------------- pooling (batch sorted -> run-accumulate) ----------------
#define PNB 128
__global__ void pool_kernel(const int* __restrict__ batch,
                            const float* __restrict__ act) {
    int c = threadIdx.x;       // 0..63
    int n0 = blockIdx.x * PNB;
    int n1 = min(n0 + PNB, N_NODES);
    int curg = batch[n0];
    float acc = 0.f, cnt = 0.f;
    for (int n = n0; n < n1; n++) {
        int gidx = batch[n];
        if (gidx != curg) {
            atomicAdd(&g_pool[curg * 64 + c], acc);
            if (c == 0) atomicAdd(&g_cnt[curg], cnt);
            acc = 0.f; cnt = 0.f; curg = gidx;
        }
        acc += act[n * 64 + c];
        cnt += 1.f;
    }
    atomicAdd(&g_pool[curg * 64 + c], acc);
    if (c == 0) atomicAdd(&g_cnt[curg], cnt);
}

__global__ void finalize_kernel(const float* __restrict__ lin_w,
                                const float* __restrict__ lin_b,
                                float* __restrict__ out) {
    int g = threadIdx.x;   // 64 threads
    float cnt = fmaxf(g_cnt[g], 1.f);
    float s = 0.f;
    for (int c = 0; c < 64; c++)
        s += g_pool[g * 64 + c] * lin_w[c];
    out[g] = s / cnt + lin_b[0];
}

// ---------------- launch ----------------
extern "C" void kernel_launch(void* const* d_in, const int* in_sizes, int n_in,
                              void* d_out, int out_size) {
    (void)in_sizes; (void)n_in; (void)out_size;
    const float* x      = (const float*)d_in[0];
    const int*   ei     = (const int*)  d_in[1];
    const int*   batch  = (const int*)  d_in[2];
    const float* W0     = (const float*)d_in[3];
    const float* asrc0  = (const float*)d_in[4];
    const float* adst0  = (const float*)d_in[5];
    const float* b0     = (const float*)d_in[6];
    const float* W1     = (const float*)d_in[7];
    const float* asrc1  = (const float*)d_in[8];
    const float* adst1  = (const float*)d_in[9];
    const float* b1     = (const float*)d_in[10];
    const float* W2     = (const float*)d_in[11];
    const float* asrc2  = (const float*)d_in[12];
    const float* adst2  = (const float*)d_in[13];
    const float* b2     = (const float*)d_in[14];
    const float* lin_w  = (const float*)d_in[15];
    const float* lin_b  = (const float*)d_in[16];
    float* out = (float*)d_out;

    void *p_act_v, *p_deg_v, *p_pool_v, *p_cnt_v;
    cudaGetSymbolAddress(&p_act_v, g_act);
    cudaGetSymbolAddress(&p_deg_v, g_deg);
    cudaGetSymbolAddress(&p_pool_v, g_pool);
    cudaGetSymbolAddress(&p_cnt_v, g_cnt);
    float* p_act = (float*)p_act_v;

    cudaFuncSetAttribute(mma_gemm_attn_kernel, cudaFuncAttributeMaxDynamicSharedMemorySize, GEMM_SMEM);

    cudaMemsetAsync(p_deg_v, 0, N_NODES * sizeof(int));
    cudaMemsetAsync(p_pool_v, 0, NGRAPH * 64 * sizeof(float));
    cudaMemsetAsync(p_cnt_v, 0, NGRAPH * sizeof(float));

    count_deg_kernel<<<(ET + 255) / 256, 256>>>(ei);
    deg_blocksum_kernel<<<NBLK_SCAN, 256>>>();
    bsum_scan_kernel<<<1, 256>>>();
    rowptr_fill_kernel<<<NBLK_SCAN, 256>>>();
    fill_csr_kernel<<<(ET + 255) / 256, 256>>>(ei);

    dim3 grid_big(4, (N_NODES + GBM - 1) / GBM);
    dim3 grid_sml(1, (N_NODES + GBM - 1) / GBM);

    // ----- layer 0: 128 -> 256 -----
    mma_gemm_attn_kernel<<<grid_big, 256, GEMM_SMEM>>>(x, W0, asrc0, adst0, N_NODES, 128, 256, 4);
    gat_agg_kernel<4, true><<<(N_NODES + 3) / 4, 128>>>(b0, p_act);
    // ----- layer 1: 256 -> 256 -----
    mma_gemm_attn_kernel<<<grid_big, 256, GEMM_SMEM>>>(p_act, W1, asrc1, adst1, N_NODES, 256, 256, 4);
    gat_agg_kernel<4, true><<<(N_NODES + 3) / 4, 128>>>(b1, p_act);
    // ----- layer 2: 256 -> 64 -----
    mma_gemm_attn_kernel<<<grid_sml, 256, GEMM_SMEM>>>(p_act, W2, asrc2, adst2, N_NODES, 256, 64, 1);
    gat_agg_kernel<1, false><<<(N_NODES + 15) / 16, 128>>>(b2, p_act);

    // ----- global mean pool + linear -----
    pool_kernel<<<(N_NODES + PNB - 1) / PNB, 64>>>(batch, p_act);
    finalize_kernel<<<1, 64>>>(lin_w, lin_b, out);
}

// round 5
// speedup vs baseline: 2.7387x; 1.3551x over previous
#include <cuda_runtime.h>
#include <cuda_fp16.h>
#include <math.h>

// ---------------- problem constants ----------------
#define N_NODES 50000
#define E_EDGES 800000
#define ET (E_EDGES + N_NODES)   // edges + self loops = 850000
#define NGRAPH 64
#define NEG_SLOPE 0.2f
#define NBLK_SCAN 196            // ceil(50000/256)

// ---------------- device scratch ----------------
__device__ __half g_xh  [N_NODES * 128];  // fp16 copy of input x
__device__ __half g_hth [N_NODES * 256];  // fp16 GEMM output h (agg gather operand)
__device__ __half g_acth[N_NODES * 256];  // fp16 activation (next GEMM's A)
__device__ float  g_act [N_NODES * 64];   // fp32 layer-2 activation (for pooling)
__device__ float  g_esrc[N_NODES * 4];
__device__ float  g_edst[N_NODES * 4];
__device__ int    g_deg   [N_NODES];
__device__ int    g_rowptr[N_NODES + 1];
__device__ int    g_cursor[N_NODES];
__device__ int    g_srclist[ET];
__device__ int    g_bsum[256];
__device__ int    g_boff[256];
__device__ float  g_pool[NGRAPH * 64];
__device__ float  g_cnt [NGRAPH];

// ---------------- input conversion ----------------
__global__ void convert_x_kernel(const float* __restrict__ x) {
    int i = blockIdx.x * blockDim.x + threadIdx.x;   // per 4 floats
    if (i >= N_NODES * 128 / 4) return;
    float4 v = reinterpret_cast<const float4*>(x)[i];
    __half2 h0 = __floats2half2_rn(v.x, v.y);
    __half2 h1 = __floats2half2_rn(v.z, v.w);
    reinterpret_cast<__half2*>(g_xh)[2 * i]     = h0;
    reinterpret_cast<__half2*>(g_xh)[2 * i + 1] = h1;
}

// ---------------- CSR build (by destination) ----------------
__global__ void count_deg_kernel(const int* __restrict__ ei) {
    int e = blockIdx.x * blockDim.x + threadIdx.x;
    if (e >= ET) return;
    int d = (e < E_EDGES) ? ei[E_EDGES + e] : (e - E_EDGES);
    atomicAdd(&g_deg[d], 1);
}

__global__ void deg_blocksum_kernel() {
    __shared__ int sm[256];
    int idx = blockIdx.x * 256 + threadIdx.x;
    sm[threadIdx.x] = (idx < N_NODES) ? g_deg[idx] : 0;
    __syncthreads();
    for (int o = 128; o > 0; o >>= 1) {
        if (threadIdx.x < o) sm[threadIdx.x] += sm[threadIdx.x + o];
        __syncthreads();
    }
    if (threadIdx.x == 0) g_bsum[blockIdx.x] = sm[0];
}

__global__ void bsum_scan_kernel() {
    __shared__ int sm[256];
    int t = threadIdx.x;
    sm[t] = (t < NBLK_SCAN) ? g_bsum[t] : 0;
    __syncthreads();
    for (int o = 1; o < 256; o <<= 1) {
        int v = (t >= o) ? sm[t - o] : 0;
        __syncthreads();
        sm[t] += v;
        __syncthreads();
    }
    g_boff[t] = (t == 0) ? 0 : sm[t - 1];
    if (t == NBLK_SCAN - 1) g_rowptr[N_NODES] = sm[t];
}

__global__ void rowptr_fill_kernel() {
    __shared__ int sm[256];
    int t = threadIdx.x;
    int idx = blockIdx.x * 256 + t;
    int v = (idx < N_NODES) ? g_deg[idx] : 0;
    sm[t] = v;
    __syncthreads();
    for (int o = 1; o < 256; o <<= 1) {
        int u = (t >= o) ? sm[t - o] : 0;
        __syncthreads();
        sm[t] += u;
        __syncthreads();
    }
    if (idx < N_NODES) {
        int excl = g_boff[blockIdx.x] + sm[t] - v;
        g_rowptr[idx] = excl;
        g_cursor[idx] = excl;
    }
}

__global__ void fill_csr_kernel(const int* __restrict__ ei) {
    int e = blockIdx.x * blockDim.x + threadIdx.x;
    if (e >= ET) return;
    int s, d;
    if (e < E_EDGES) { s = ei[e]; d = ei[E_EDGES + e]; }
    else             { s = e - E_EDGES; d = s; }
    int pos = atomicAdd(&g_cursor[d], 1);
    g_srclist[pos] = s;
}

// ---------------- fp16 tensor-core GEMM + fused attention epilogue ----------------
__device__ __forceinline__ void mma_f16(float* c, const unsigned* a, const unsigned* b) {
    asm volatile(
        "mma.sync.aligned.m16n8k16.row.col.f32.f16.f16.f32 "
        "{%0,%1,%2,%3},{%4,%5,%6,%7},{%8,%9},{%0,%1,%2,%3};"
        : "+f"(c[0]), "+f"(c[1]), "+f"(c[2]), "+f"(c[3])
        : "r"(a[0]), "r"(a[1]), "r"(a[2]), "r"(a[3]), "r"(b[0]), "r"(b[1]));
}

#define GBM 128
#define GBN 64
#define GBK 32
#define A_STRH 40
#define B_STRH 40

// A: fp16 [M,K] row-major. B: fp32 weights [K,Nd]. Outputs fp16 h + e_src/e_dst.
__global__ __launch_bounds__(256, 2)
void hgemm_attn_kernel(const __half* __restrict__ A, const float* __restrict__ B,
                       const float* __restrict__ asrc, const float* __restrict__ adst,
                       int M, int K, int Nd, int H) {
    __shared__ __half As[2][GBM * A_STRH];   // 20480 B
    __shared__ __half Bs[2][GBN * B_STRH];   // 10240 B

    const int tid  = threadIdx.x;
    const int warp = tid >> 5, lane = tid & 31;
    const int wm = warp >> 1, wn = warp & 1;
    const int row0 = blockIdx.y * GBM, col0 = blockIdx.x * GBN;
    const int head = blockIdx.x;
    const int g = lane >> 2, tg = lane & 3;
    const int ar = tid >> 1, ahf = (tid & 1) * 16;   // A: 2 x uint4 per thread
    const int bn = tid & 63, bkq = (tid >> 6) * 8;   // B: 8 k's for one n

    float acc[2][4][4] = {};
    uint4 a_pre[2];
    float b_pre[8];

    auto ldg = [&](int k0) {
        const __half* ap = &A[(size_t)(row0 + ar) * K + k0 + ahf];
        bool ok = (row0 + ar) < M;
        a_pre[0] = ok ? *(const uint4*)ap       : make_uint4(0, 0, 0, 0);
        a_pre[1] = ok ? *(const uint4*)(ap + 8) : make_uint4(0, 0, 0, 0);
#pragma unroll
        for (int i = 0; i < 8; i++)
            b_pre[i] = B[(size_t)(k0 + bkq + i) * Nd + col0 + bn];
    };
    auto sts = [&](int s) {
        *(uint4*)&As[s][ar * A_STRH + ahf]     = a_pre[0];
        *(uint4*)&As[s][ar * A_STRH + ahf + 8] = a_pre[1];
        __half hb[8];
#pragma unroll
        for (int i = 0; i < 8; i++) hb[i] = __float2half(b_pre[i]);
        *(uint4*)&Bs[s][bn * B_STRH + bkq] = *(uint4*)hb;
    };
    auto compute = [&](int s) {
#pragma unroll
        for (int ks = 0; ks < 2; ks++) {
            int kb = ks * 16;
            unsigned afr[2][4];
#pragma unroll
            for (int mt = 0; mt < 2; mt++) {
                int r = wm * 32 + mt * 16;
                afr[mt][0] = *(unsigned*)&As[s][(r + g)     * A_STRH + kb + 2 * tg];
                afr[mt][1] = *(unsigned*)&As[s][(r + g + 8) * A_STRH + kb + 2 * tg];
                afr[mt][2] = *(unsigned*)&As[s][(r + g)     * A_STRH + kb + 2 * tg + 8];
                afr[mt][3] = *(unsigned*)&As[s][(r + g + 8) * A_STRH + kb + 2 * tg + 8];
            }
            unsigned bfr[4][2];
#pragma unroll
            for (int nt = 0; nt < 4; nt++) {
                int c = wn * 32 + nt * 8 + g;
                bfr[nt][0] = *(unsigned*)&Bs[s][c * B_STRH + kb + 2 * tg];
                bfr[nt][1] = *(unsigned*)&Bs[s][c * B_STRH + kb + 2 * tg + 8];
            }
#pragma unroll
            for (int mt = 0; mt < 2; mt++)
#pragma unroll
                for (int nt = 0; nt < 4; nt++)
                    mma_f16(acc[mt][nt], afr[mt], bfr[nt]);
        }
    };

    ldg(0); sts(0); __syncthreads();
    int nk = K / GBK;
    for (int i = 0; i < nk; i++) {
        if (i + 1 < nk) ldg((i + 1) * GBK);
        compute(i & 1);
        if (i + 1 < nk) sts((i + 1) & 1);
        __syncthreads();
    }

    // ---- epilogue 1: fp16 feature store ----
#pragma unroll
    for (int mt = 0; mt < 2; mt++)
#pragma unroll
        for (int nt = 0; nt < 4; nt++) {
            int r = row0 + wm * 32 + mt * 16 + g;
            int c = col0 + wn * 32 + nt * 8 + 2 * tg;
            if (r < M)
                *(__half2*)&g_hth[(size_t)r * Nd + c] =
                    __floats2half2_rn(acc[mt][nt][0], acc[mt][nt][1]);
            if (r + 8 < M)
                *(__half2*)&g_hth[(size_t)(r + 8) * Nd + c] =
                    __floats2half2_rn(acc[mt][nt][2], acc[mt][nt][3]);
        }

    // ---- epilogue 2: attention coefficients ----
    float ps[2][2] = {}, pd[2][2] = {};
    const int hb = head * 64;
#pragma unroll
    for (int nt = 0; nt < 4; nt++) {
        int cl = wn * 32 + nt * 8 + 2 * tg;
        float as0 = asrc[hb + cl], as1 = asrc[hb + cl + 1];
        float ad0 = adst[hb + cl], ad1 = adst[hb + cl + 1];
#pragma unroll
        for (int mt = 0; mt < 2; mt++) {
            ps[mt][0] += acc[mt][nt][0] * as0 + acc[mt][nt][1] * as1;
            ps[mt][1] += acc[mt][nt][2] * as0 + acc[mt][nt][3] * as1;
            pd[mt][0] += acc[mt][nt][0] * ad0 + acc[mt][nt][1] * ad1;
            pd[mt][1] += acc[mt][nt][2] * ad0 + acc[mt][nt][3] * ad1;
        }
    }
#pragma unroll
    for (int o = 1; o < 4; o <<= 1) {
#pragma unroll
        for (int mt = 0; mt < 2; mt++)
#pragma unroll
            for (int rr = 0; rr < 2; rr++) {
                ps[mt][rr] += __shfl_xor_sync(0xFFFFFFFFu, ps[mt][rr], o);
                pd[mt][rr] += __shfl_xor_sync(0xFFFFFFFFu, pd[mt][rr], o);
            }
    }
    float* sm_src = (float*)&As[0][0];     // reuse smem: [2][128] + [2][128]
    float* sm_dst = sm_src + 2 * GBM;
    __syncthreads();
    if (tg == 0) {
#pragma unroll
        for (int mt = 0; mt < 2; mt++)
#pragma unroll
            for (int rr = 0; rr < 2; rr++) {
                int rl = wm * 32 + mt * 16 + g + rr * 8;
                sm_src[wn * GBM + rl] = ps[mt][rr];
                sm_dst[wn * GBM + rl] = pd[mt][rr];
            }
    }
    __syncthreads();
    if (tid < GBM) {
        int r = row0 + tid;
        if (r < M) {
            g_esrc[(size_t)r * H + head] = sm_src[tid] + sm_src[GBM + tid];
            g_edst[(size_t)r * H + head] = sm_dst[tid] + sm_dst[GBM + tid];
        }
    }
}

// ---------------- fused gather softmax + aggregation ----------------
// OUT16: write fp16 activation (next GEMM input); else fp32 (pooling input).
template <int H, bool RELU, bool OUT16>
__global__ void gat_agg_kernel(const float* __restrict__ bias,
                               float* __restrict__ outf) {
    constexpr int HC  = H * 64;
    constexpr int TPG = HC / 8;
    constexpr int NPB = 128 / TPG;
    int node = blockIdx.x * NPB + threadIdx.x / TPG;
    if (node >= N_NODES) return;
    int t = threadIdx.x % TPG;
    int head = (H == 1) ? 0 : (t >> 3);

    int beg = g_rowptr[node];
    int end = g_rowptr[node + 1];
    float ed = g_edst[node * H + head];

    float acc[8] = {};
    float denom = 0.f;
    const uint4* hv4 = reinterpret_cast<const uint4*>(g_hth);

    int   s_nx  = (beg < end) ? g_srclist[beg] : 0;
    float es_nx = (beg < end) ? g_esrc[s_nx * H + head] : 0.f;
    for (int i = beg; i < end; i++) {
        int   s  = s_nx;
        float es = es_nx;
        if (i + 1 < end) {                    // prefetch next edge
            s_nx  = g_srclist[i + 1];
            es_nx = g_esrc[s_nx * H + head];
        }
        float e = es + ed;
        e = (e > 0.f) ? e : NEG_SLOPE * e;
        float ex = __expf(e);                 // max-shift cancels in alpha
        denom += ex;
        uint4 u = hv4[(size_t)s * TPG + t];
        unsigned uu[4] = {u.x, u.y, u.z, u.w};
#pragma unroll
        for (int k = 0; k < 4; k++) {
            __half2 h2 = *reinterpret_cast<__half2*>(&uu[k]);
            float2 f = __half22float2(h2);
            acc[2 * k]     = fmaf(ex, f.x, acc[2 * k]);
            acc[2 * k + 1] = fmaf(ex, f.y, acc[2 * k + 1]);
        }
    }

    float inv = 1.f / (denom + 1e-16f);
    int c0 = t * 8;
    float o[8];
#pragma unroll
    for (int k = 0; k < 8; k++) {
        float v = acc[k] * inv + bias[c0 + k];
        o[k] = RELU ? fmaxf(v, 0.f) : v;
    }
    if (OUT16) {
        __half hb[8];
#pragma unroll
        for (int k = 0; k < 8; k++) hb[k] = __float2half(o[k]);
        *(uint4*)&g_acth[(size_t)node * HC + c0] = *(uint4*)hb;
    } else {
        float4* ob = reinterpret_cast<float4*>(&outf[(size_t)node * HC + c0]);
        ob[0] = make_float4(o[0], o[1], o[2], o[3]);
        ob[1] = make_float4(o[4], o[5], o[6], o[7]);
    }
}

// ---------------- pooling (batch sorted -> run-accumulate) ----------------
#define PNB 128
__global__ void pool_kernel(const int* __restrict__ batch,
                            const float* __restrict__ act) {
    int c = threadIdx.x;       // 0..63
    int n0 = blockIdx.x * PNB;
    int n1 = min(n0 + PNB, N_NODES);
    int curg = batch[n0];
    float acc = 0.f, cnt = 0.f;
    for (int n = n0; n < n1; n++) {
        int gidx = batch[n];
        if (gidx != curg) {
            atomicAdd(&g_pool[curg * 64 + c], acc);
            if (c == 0) atomicAdd(&g_cnt[curg], cnt);
            acc = 0.f; cnt = 0.f; curg = gidx;
        }
        acc += act[n * 64 + c];
        cnt += 1.f;
    }
    atomicAdd(&g_pool[curg * 64 + c], acc);
    if (c == 0) atomicAdd(&g_cnt[curg], cnt);
}

__global__ void finalize_kernel(const float* __restrict__ lin_w,
                                const float* __restrict__ lin_b,
                                float* __restrict__ out) {
    int g = threadIdx.x;   // 64 threads
    float cnt = fmaxf(g_cnt[g], 1.f);
    float s = 0.f;
    for (int c = 0; c < 64; c++)
        s += g_pool[g * 64 + c] * lin_w[c];
    out[g] = s / cnt + lin_b[0];
}

// ---------------- launch ----------------
extern "C" void kernel_launch(void* const* d_in, const int* in_sizes, int n_in,
                              void* d_out, int out_size) {
    (void)in_sizes; (void)n_in; (void)out_size;
    const float* x      = (const float*)d_in[0];
    const int*   ei     = (const int*)  d_in[1];
    const int*   batch  = (const int*)  d_in[2];
    const float* W0     = (const float*)d_in[3];
    const float* asrc0  = (const float*)d_in[4];
    const float* adst0  = (const float*)d_in[5];
    const float* b0     = (const float*)d_in[6];
    const float* W1     = (const float*)d_in[7];
    const float* asrc1  = (const float*)d_in[8];
    const float* adst1  = (const float*)d_in[9];
    const float* b1     = (const float*)d_in[10];
    const float* W2     = (const float*)d_in[11];
    const float* asrc2  = (const float*)d_in[12];
    const float* adst2  = (const float*)d_in[13];
    const float* b2     = (const float*)d_in[14];
    const float* lin_w  = (const float*)d_in[15];
    const float* lin_b  = (const float*)d_in[16];
    float* out = (float*)d_out;

    static cudaStream_t s2 = nullptr;
    static cudaEvent_t ev1 = nullptr, ev2 = nullptr;
    if (!s2) {
        cudaStreamCreateWithFlags(&s2, cudaStreamNonBlocking);
        cudaEventCreateWithFlags(&ev1, cudaEventDisableTiming);
        cudaEventCreateWithFlags(&ev2, cudaEventDisableTiming);
    }

    void *p_xh_v, *p_acth_v, *p_act_v, *p_deg_v, *p_pool_v, *p_cnt_v;
    cudaGetSymbolAddress(&p_xh_v, g_xh);
    cudaGetSymbolAddress(&p_acth_v, g_acth);
    cudaGetSymbolAddress(&p_act_v, g_act);
    cudaGetSymbolAddress(&p_deg_v, g_deg);
    cudaGetSymbolAddress(&p_pool_v, g_pool);
    cudaGetSymbolAddress(&p_cnt_v, g_cnt);
    const __half* p_xh   = (const __half*)p_xh_v;
    const __half* p_acth = (const __half*)p_acth_v;
    float* p_act = (float*)p_act_v;

    // ---- fork: CSR build on side stream, overlapped with convert+GEMM0 ----
    cudaEventRecord(ev1, 0);
    cudaStreamWaitEvent(s2, ev1, 0);
    cudaMemsetAsync(p_deg_v, 0, N_NODES * sizeof(int), s2);
    count_deg_kernel<<<(ET + 255) / 256, 256, 0, s2>>>(ei);
    deg_blocksum_kernel<<<NBLK_SCAN, 256, 0, s2>>>();
    bsum_scan_kernel<<<1, 256, 0, s2>>>();
    rowptr_fill_kernel<<<NBLK_SCAN, 256, 0, s2>>>();
    fill_csr_kernel<<<(ET + 255) / 256, 256, 0, s2>>>(ei);
    cudaEventRecord(ev2, s2);

    // ---- main stream ----
    cudaMemsetAsync(p_pool_v, 0, NGRAPH * 64 * sizeof(float));
    cudaMemsetAsync(p_cnt_v, 0, NGRAPH * sizeof(float));
    convert_x_kernel<<<(N_NODES * 128 / 4 + 255) / 256, 256>>>(x);

    dim3 grid_big(4, (N_NODES + GBM - 1) / GBM);
    dim3 grid_sml(1, (N_NODES + GBM - 1) / GBM);

    // layer 0 GEMM overlaps CSR build
    hgemm_attn_kernel<<<grid_big, 256>>>(p_xh, W0, asrc0, adst0, N_NODES, 128, 256, 4);
    cudaStreamWaitEvent(0, ev2, 0);     // join: agg needs CSR
    gat_agg_kernel<4, true, true><<<(N_NODES + 3) / 4, 128>>>(b0, nullptr);

    hgemm_attn_kernel<<<grid_big, 256>>>(p_acth, W1, asrc1, adst1, N_NODES, 256, 256, 4);
    gat_agg_kernel<4, true, true><<<(N_NODES + 3) / 4, 128>>>(b1, nullptr);

    hgemm_attn_kernel<<<grid_sml, 256>>>(p_acth, W2, asrc2, adst2, N_NODES, 256, 64, 1);
    gat_agg_kernel<1, false, false><<<(N_NODES + 15) / 16, 128>>>(b2, p_act);

    pool_kernel<<<(N_NODES + PNB - 1) / PNB, 64>>>(batch, p_act);
    finalize_kernel<<<1, 64>>>(lin_w, lin_b, out);
}

// round 6
// speedup vs baseline: 3.0299x; 1.1063x over previous
#include <cuda_runtime.h>
#include <cuda_fp16.h>
#include <math.h>

// ---------------- problem constants ----------------
#define N_NODES 50000
#define E_EDGES 800000
#define ET (E_EDGES + N_NODES)   // edges + self loops = 850000
#define NGRAPH 64
#define NEG_SLOPE 0.2f
#define NBLK_SCAN 196            // ceil(50000/256)

// ---------------- device scratch ----------------
__device__ __half g_xh  [N_NODES * 128];  // fp16 copy of input x
__device__ __half g_hth [N_NODES * 256];  // fp16 GEMM output h (agg gather operand)
__device__ __half g_acth[N_NODES * 256];  // fp16 activation (next GEMM's A)
__device__ float  g_act [N_NODES * 64];   // fp32 layer-2 activation (for pooling)
__device__ float  g_esrc[N_NODES * 4];
__device__ float  g_edst[N_NODES * 4];
__device__ int    g_deg   [N_NODES];
__device__ int    g_rowptr[N_NODES + 1];
__device__ int    g_cursor[N_NODES];
__device__ int    g_srclist[ET];
__device__ int    g_bsum[256];
__device__ int    g_boff[256];
__device__ float  g_pool[NGRAPH * 64];
__device__ float  g_cnt [NGRAPH];

// ---------------- input conversion ----------------
__global__ void convert_x_kernel(const float* __restrict__ x) {
    int i = blockIdx.x * blockDim.x + threadIdx.x;   // per 4 floats
    if (i >= N_NODES * 128 / 4) return;
    float4 v = reinterpret_cast<const float4*>(x)[i];
    __half2 h0 = __floats2half2_rn(v.x, v.y);
    __half2 h1 = __floats2half2_rn(v.z, v.w);
    reinterpret_cast<__half2*>(g_xh)[2 * i]     = h0;
    reinterpret_cast<__half2*>(g_xh)[2 * i + 1] = h1;
}

// ---------------- CSR build (by destination) ----------------
__global__ void count_deg_kernel(const int* __restrict__ ei) {
    int e = blockIdx.x * blockDim.x + threadIdx.x;
    if (e >= ET) return;
    int d = (e < E_EDGES) ? ei[E_EDGES + e] : (e - E_EDGES);
    atomicAdd(&g_deg[d], 1);
}

__global__ void deg_blocksum_kernel() {
    __shared__ int sm[256];
    int idx = blockIdx.x * 256 + threadIdx.x;
    sm[threadIdx.x] = (idx < N_NODES) ? g_deg[idx] : 0;
    __syncthreads();
    for (int o = 128; o > 0; o >>= 1) {
        if (threadIdx.x < o) sm[threadIdx.x] += sm[threadIdx.x + o];
        __syncthreads();
    }
    if (threadIdx.x == 0) g_bsum[blockIdx.x] = sm[0];
}

__global__ void bsum_scan_kernel() {
    __shared__ int sm[256];
    int t = threadIdx.x;
    sm[t] = (t < NBLK_SCAN) ? g_bsum[t] : 0;
    __syncthreads();
    for (int o = 1; o < 256; o <<= 1) {
        int v = (t >= o) ? sm[t - o] : 0;
        __syncthreads();
        sm[t] += v;
        __syncthreads();
    }
    g_boff[t] = (t == 0) ? 0 : sm[t - 1];
    if (t == NBLK_SCAN - 1) g_rowptr[N_NODES] = sm[t];
}

__global__ void rowptr_fill_kernel() {
    __shared__ int sm[256];
    int t = threadIdx.x;
    int idx = blockIdx.x * 256 + t;
    int v = (idx < N_NODES) ? g_deg[idx] : 0;
    sm[t] = v;
    __syncthreads();
    for (int o = 1; o < 256; o <<= 1) {
        int u = (t >= o) ? sm[t - o] : 0;
        __syncthreads();
        sm[t] += u;
        __syncthreads();
    }
    if (idx < N_NODES) {
        int excl = g_boff[blockIdx.x] + sm[t] - v;
        g_rowptr[idx] = excl;
        g_cursor[idx] = excl;
    }
}

__global__ void fill_csr_kernel(const int* __restrict__ ei) {
    int e = blockIdx.x * blockDim.x + threadIdx.x;
    if (e >= ET) return;
    int s, d;
    if (e < E_EDGES) { s = ei[e]; d = ei[E_EDGES + e]; }
    else             { s = e - E_EDGES; d = s; }
    int pos = atomicAdd(&g_cursor[d], 1);
    g_srclist[pos] = s;
}

// ---------------- fp16 tensor-core GEMM + fused attention epilogue ----------------
__device__ __forceinline__ void mma_f16(float* c, const unsigned* a, const unsigned* b) {
    asm volatile(
        "mma.sync.aligned.m16n8k16.row.col.f32.f16.f16.f32 "
        "{%0,%1,%2,%3},{%4,%5,%6,%7},{%8,%9},{%0,%1,%2,%3};"
        : "+f"(c[0]), "+f"(c[1]), "+f"(c[2]), "+f"(c[3])
        : "r"(a[0]), "r"(a[1]), "r"(a[2]), "r"(a[3]), "r"(b[0]), "r"(b[1]));
}

__device__ __forceinline__ void ldsm_x4(unsigned& r0, unsigned& r1, unsigned& r2,
                                        unsigned& r3, unsigned addr) {
    asm volatile("ldmatrix.sync.aligned.m8n8.x4.shared.b16 {%0,%1,%2,%3}, [%4];"
                 : "=r"(r0), "=r"(r1), "=r"(r2), "=r"(r3) : "r"(addr));
}

#define GBM 128
#define GBN 64
#define GBK 32
#define A_STRH 40
#define B_STRH 40

// A: fp16 [M,K] row-major. B: fp32 weights [K,Nd]. Outputs fp16 h + e_src/e_dst.
__global__ __launch_bounds__(256, 2)
void hgemm_attn_kernel(const __half* __restrict__ A, const float* __restrict__ B,
                       const float* __restrict__ asrc, const float* __restrict__ adst,
                       int M, int K, int Nd, int H) {
    __shared__ __half As[2][GBM * A_STRH];   // 20480 B
    __shared__ __half Bs[2][GBN * B_STRH];   // 10240 B

    const int tid  = threadIdx.x;
    const int warp = tid >> 5, lane = tid & 31;
    const int wm = warp >> 1, wn = warp & 1;
    const int row0 = blockIdx.y * GBM, col0 = blockIdx.x * GBN;
    const int head = blockIdx.x;
    const int g = lane >> 2, tg = lane & 3;
    const int ar = tid >> 1, ahf = (tid & 1) * 16;   // A: 2 x uint4 per thread
    const int bn = tid & 63, bkq = (tid >> 6) * 8;   // B: 8 k's for one n

    // ldmatrix per-lane shared offsets (in halfs)
    const unsigned As_sh = (unsigned)__cvta_generic_to_shared(&As[0][0]);
    const unsigned Bs_sh = (unsigned)__cvta_generic_to_shared(&Bs[0][0]);
    const int a_lsel = (lane & 15) * A_STRH + (lane >> 4) * 8;
    const int b_lsel = (((lane >> 4) & 1) * 8 + (lane & 7)) * B_STRH + ((lane >> 3) & 1) * 8;

    float acc[2][4][4] = {};
    uint4 a_pre[2];
    float b_pre[8];

    auto ldg = [&](int k0) {
        const __half* ap = &A[(size_t)(row0 + ar) * K + k0 + ahf];
        bool ok = (row0 + ar) < M;
        a_pre[0] = ok ? *(const uint4*)ap       : make_uint4(0, 0, 0, 0);
        a_pre[1] = ok ? *(const uint4*)(ap + 8) : make_uint4(0, 0, 0, 0);
#pragma unroll
        for (int i = 0; i < 8; i++)
            b_pre[i] = B[(size_t)(k0 + bkq + i) * Nd + col0 + bn];
    };
    auto sts = [&](int s) {
        *(uint4*)&As[s][ar * A_STRH + ahf]     = a_pre[0];
        *(uint4*)&As[s][ar * A_STRH + ahf + 8] = a_pre[1];
        __half hb[8];
#pragma unroll
        for (int i = 0; i < 8; i++) hb[i] = __float2half(b_pre[i]);
        *(uint4*)&Bs[s][bn * B_STRH + bkq] = *(uint4*)hb;
    };
    auto compute = [&](int s) {
#pragma unroll
        for (int ks = 0; ks < 2; ks++) {
            unsigned afr[2][4];
#pragma unroll
            for (int mt = 0; mt < 2; mt++) {
                unsigned addr = As_sh +
                    (unsigned)((s * GBM * A_STRH) +
                               (wm * 32 + mt * 16) * A_STRH + ks * 16 + a_lsel) * 2u;
                ldsm_x4(afr[mt][0], afr[mt][1], afr[mt][2], afr[mt][3], addr);
            }
            unsigned bfr[4][2];
#pragma unroll
            for (int p = 0; p < 2; p++) {
                unsigned addr = Bs_sh +
                    (unsigned)((s * GBN * B_STRH) +
                               (wn * 32 + p * 16) * B_STRH + ks * 16 + b_lsel) * 2u;
                ldsm_x4(bfr[2 * p][0], bfr[2 * p][1], bfr[2 * p + 1][0], bfr[2 * p + 1][1], addr);
            }
#pragma unroll
            for (int mt = 0; mt < 2; mt++)
#pragma unroll
                for (int nt = 0; nt < 4; nt++)
                    mma_f16(acc[mt][nt], afr[mt], bfr[nt]);
        }
    };

    ldg(0); sts(0); __syncthreads();
    int nk = K / GBK;
    for (int i = 0; i < nk; i++) {
        if (i + 1 < nk) ldg((i + 1) * GBK);
        compute(i & 1);
        if (i + 1 < nk) sts((i + 1) & 1);
        __syncthreads();
    }

    // ---- epilogue 1: fp16 feature store ----
#pragma unroll
    for (int mt = 0; mt < 2; mt++)
#pragma unroll
        for (int nt = 0; nt < 4; nt++) {
            int r = row0 + wm * 32 + mt * 16 + g;
            int c = col0 + wn * 32 + nt * 8 + 2 * tg;
            if (r < M)
                *(__half2*)&g_hth[(size_t)r * Nd + c] =
                    __floats2half2_rn(acc[mt][nt][0], acc[mt][nt][1]);
            if (r + 8 < M)
                *(__half2*)&g_hth[(size_t)(r + 8) * Nd + c] =
                    __floats2half2_rn(acc[mt][nt][2], acc[mt][nt][3]);
        }

    // ---- epilogue 2: attention coefficients ----
    float ps[2][2] = {}, pd[2][2] = {};
    const int hb = head * 64;
#pragma unroll
    for (int nt = 0; nt < 4; nt++) {
        int cl = wn * 32 + nt * 8 + 2 * tg;
        float as0 = asrc[hb + cl], as1 = asrc[hb + cl + 1];
        float ad0 = adst[hb + cl], ad1 = adst[hb + cl + 1];
#pragma unroll
        for (int mt = 0; mt < 2; mt++) {
            ps[mt][0] += acc[mt][nt][0] * as0 + acc[mt][nt][1] * as1;
            ps[mt][1] += acc[mt][nt][2] * as0 + acc[mt][nt][3] * as1;
            pd[mt][0] += acc[mt][nt][0] * ad0 + acc[mt][nt][1] * ad1;
            pd[mt][1] += acc[mt][nt][2] * ad0 + acc[mt][nt][3] * ad1;
        }
    }
#pragma unroll
    for (int o = 1; o < 4; o <<= 1) {
#pragma unroll
        for (int mt = 0; mt < 2; mt++)
#pragma unroll
            for (int rr = 0; rr < 2; rr++) {
                ps[mt][rr] += __shfl_xor_sync(0xFFFFFFFFu, ps[mt][rr], o);
                pd[mt][rr] += __shfl_xor_sync(0xFFFFFFFFu, pd[mt][rr], o);
            }
    }
    float* sm_src = (float*)&As[0][0];     // reuse smem: [2][128] + [2][128]
    float* sm_dst = sm_src + 2 * GBM;
    __syncthreads();
    if (tg == 0) {
#pragma unroll
        for (int mt = 0; mt < 2; mt++)
#pragma unroll
            for (int rr = 0; rr < 2; rr++) {
                int rl = wm * 32 + mt * 16 + g + rr * 8;
                sm_src[wn * GBM + rl] = ps[mt][rr];
                sm_dst[wn * GBM + rl] = pd[mt][rr];
            }
    }
    __syncthreads();
    if (tid < GBM) {
        int r = row0 + tid;
        if (r < M) {
            g_esrc[(size_t)r * H + head] = sm_src[tid] + sm_src[GBM + tid];
            g_edst[(size_t)r * H + head] = sm_dst[tid] + sm_dst[GBM + tid];
        }
    }
}

// ---------------- fused gather softmax + aggregation (unroll x2) ----------------
// OUT16: write fp16 activation (next GEMM input); else fp32 (pooling input).
template <int H, bool RELU, bool OUT16>
__global__ void gat_agg_kernel(const float* __restrict__ bias,
                               float* __restrict__ outf) {
    constexpr int HC  = H * 64;
    constexpr int TPG = HC / 8;
    constexpr int NPB = 128 / TPG;
    int node = blockIdx.x * NPB + threadIdx.x / TPG;
    if (node >= N_NODES) return;
    int t = threadIdx.x % TPG;
    int head = (H == 1) ? 0 : (t >> 3);

    int beg = g_rowptr[node];
    int end = g_rowptr[node + 1];
    float ed = g_edst[node * H + head];

    float acc[8] = {};
    float denom = 0.f;
    const uint4* hv4 = reinterpret_cast<const uint4*>(g_hth);

    int i = beg;
    for (; i + 2 <= end; i += 2) {
        int s0 = g_srclist[i];
        int s1 = g_srclist[i + 1];
        float es0 = g_esrc[s0 * H + head];
        float es1 = g_esrc[s1 * H + head];
        uint4 u0 = hv4[(size_t)s0 * TPG + t];
        uint4 u1 = hv4[(size_t)s1 * TPG + t];
        float e0 = es0 + ed; e0 = (e0 > 0.f) ? e0 : NEG_SLOPE * e0;
        float e1 = es1 + ed; e1 = (e1 > 0.f) ? e1 : NEG_SLOPE * e1;
        float x0 = __expf(e0);
        float x1 = __expf(e1);
        denom += x0;
        denom += x1;
        unsigned uu0[4] = {u0.x, u0.y, u0.z, u0.w};
        unsigned uu1[4] = {u1.x, u1.y, u1.z, u1.w};
#pragma unroll
        for (int k = 0; k < 4; k++) {
            float2 f0 = __half22float2(*reinterpret_cast<__half2*>(&uu0[k]));
            float2 f1 = __half22float2(*reinterpret_cast<__half2*>(&uu1[k]));
            acc[2 * k]     = fmaf(x0, f0.x, acc[2 * k]);
            acc[2 * k + 1] = fmaf(x0, f0.y, acc[2 * k + 1]);
            acc[2 * k]     = fmaf(x1, f1.x, acc[2 * k]);
            acc[2 * k + 1] = fmaf(x1, f1.y, acc[2 * k + 1]);
        }
    }
    if (i < end) {
        int s = g_srclist[i];
        float e = g_esrc[s * H + head] + ed;
        e = (e > 0.f) ? e : NEG_SLOPE * e;
        float ex = __expf(e);
        denom += ex;
        uint4 u = hv4[(size_t)s * TPG + t];
        unsigned uu[4] = {u.x, u.y, u.z, u.w};
#pragma unroll
        for (int k = 0; k < 4; k++) {
            float2 f = __half22float2(*reinterpret_cast<__half2*>(&uu[k]));
            acc[2 * k]     = fmaf(ex, f.x, acc[2 * k]);
            acc[2 * k + 1] = fmaf(ex, f.y, acc[2 * k + 1]);
        }
    }

    float inv = 1.f / (denom + 1e-16f);
    int c0 = t * 8;
    float o[8];
#pragma unroll
    for (int k = 0; k < 8; k++) {
        float v = acc[k] * inv + bias[c0 + k];
        o[k] = RELU ? fmaxf(v, 0.f) : v;
    }
    if (OUT16) {
        __half hb[8];
#pragma unroll
        for (int k = 0; k < 8; k++) hb[k] = __float2half(o[k]);
        *(uint4*)&g_acth[(size_t)node * HC + c0] = *(uint4*)hb;
    } else {
        float4* ob = reinterpret_cast<float4*>(&outf[(size_t)node * HC + c0]);
        ob[0] = make_float4(o[0], o[1], o[2], o[3]);
        ob[1] = make_float4(o[4], o[5], o[6], o[7]);
    }
}

// ---------------- pooling (batch sorted -> run-accumulate) ----------------
#define PNB 128
__global__ void pool_kernel(const int* __restrict__ batch,
                            const float* __restrict__ act) {
    int c = threadIdx.x;       // 0..63
    int n0 = blockIdx.x * PNB;
    int n1 = min(n0 + PNB, N_NODES);
    int curg = batch[n0];
    float acc = 0.f, cnt = 0.f;
    for (int n = n0; n < n1; n++) {
        int gidx = batch[n];
        if (gidx != curg) {
            atomicAdd(&g_pool[curg * 64 + c], acc);
            if (c == 0) atomicAdd(&g_cnt[curg], cnt);
            acc = 0.f; cnt = 0.f; curg = gidx;
        }
        acc += act[n * 64 + c];
        cnt += 1.f;
    }
    atomicAdd(&g_pool[curg * 64 + c], acc);
    if (c == 0) atomicAdd(&g_cnt[curg], cnt);
}

__global__ void finalize_kernel(const float* __restrict__ lin_w,
                                const float* __restrict__ lin_b,
                                float* __restrict__ out) {
    int g = threadIdx.x;   // 64 threads
    float cnt = fmaxf(g_cnt[g], 1.f);
    float s = 0.f;
    for (int c = 0; c < 64; c++)
        s += g_pool[g * 64 + c] * lin_w[c];
    out[g] = s / cnt + lin_b[0];
}

// ---------------- launch ----------------
extern "C" void kernel_launch(void* const* d_in, const int* in_sizes, int n_in,
                              void* d_out, int out_size) {
    (void)in_sizes; (void)n_in; (void)out_size;
    const float* x      = (const float*)d_in[0];
    const int*   ei     = (const int*)  d_in[1];
    const int*   batch  = (const int*)  d_in[2];
    const float* W0     = (const float*)d_in[3];
    const float* asrc0  = (const float*)d_in[4];
    const float* adst0  = (const float*)d_in[5];
    const float* b0     = (const float*)d_in[6];
    const float* W1     = (const float*)d_in[7];
    const float* asrc1  = (const float*)d_in[8];
    const float* adst1  = (const float*)d_in[9];
    const float* b1     = (const float*)d_in[10];
    const float* W2     = (const float*)d_in[11];
    const float* asrc2  = (const float*)d_in[12];
    const float* adst2  = (const float*)d_in[13];
    const float* b2     = (const float*)d_in[14];
    const float* lin_w  = (const float*)d_in[15];
    const float* lin_b  = (const float*)d_in[16];
    float* out = (float*)d_out;

    static cudaStream_t s2 = nullptr;
    static cudaEvent_t ev1 = nullptr, ev2 = nullptr;
    if (!s2) {
        cudaStreamCreateWithFlags(&s2, cudaStreamNonBlocking);
        cudaEventCreateWithFlags(&ev1, cudaEventDisableTiming);
        cudaEventCreateWithFlags(&ev2, cudaEventDisableTiming);
    }

    void *p_xh_v, *p_acth_v, *p_act_v, *p_deg_v, *p_pool_v, *p_cnt_v;
    cudaGetSymbolAddress(&p_xh_v, g_xh);
    cudaGetSymbolAddress(&p_acth_v, g_acth);
    cudaGetSymbolAddress(&p_act_v, g_act);
    cudaGetSymbolAddress(&p_deg_v, g_deg);
    cudaGetSymbolAddress(&p_pool_v, g_pool);
    cudaGetSymbolAddress(&p_cnt_v, g_cnt);
    const __half* p_xh   = (const __half*)p_xh_v;
    const __half* p_acth = (const __half*)p_acth_v;
    float* p_act = (float*)p_act_v;

    // ---- fork: CSR build on side stream, overlapped with convert+GEMM0 ----
    cudaEventRecord(ev1, 0);
    cudaStreamWaitEvent(s2, ev1, 0);
    cudaMemsetAsync(p_deg_v, 0, N_NODES * sizeof(int), s2);
    count_deg_kernel<<<(ET + 255) / 256, 256, 0, s2>>>(ei);
    deg_blocksum_kernel<<<NBLK_SCAN, 256, 0, s2>>>();
    bsum_scan_kernel<<<1, 256, 0, s2>>>();
    rowptr_fill_kernel<<<NBLK_SCAN, 256, 0, s2>>>();
    fill_csr_kernel<<<(ET + 255) / 256, 256, 0, s2>>>(ei);
    cudaEventRecord(ev2, s2);

    // ---- main stream ----
    cudaMemsetAsync(p_pool_v, 0, NGRAPH * 64 * sizeof(float));
    cudaMemsetAsync(p_cnt_v, 0, NGRAPH * sizeof(float));
    convert_x_kernel<<<(N_NODES * 128 / 4 + 255) / 256, 256>>>(x);

    dim3 grid_big(4, (N_NODES + GBM - 1) / GBM);
    dim3 grid_sml(1, (N_NODES + GBM - 1) / GBM);

    // layer 0 GEMM overlaps CSR build
    hgemm_attn_kernel<<<grid_big, 256>>>(p_xh, W0, asrc0, adst0, N_NODES, 128, 256, 4);
    cudaStreamWaitEvent(0, ev2, 0);     // join: agg needs CSR
    gat_agg_kernel<4, true, true><<<(N_NODES + 3) / 4, 128>>>(b0, nullptr);

    hgemm_attn_kernel<<<grid_big, 256>>>(p_acth, W1, asrc1, adst1, N_NODES, 256, 256, 4);
    gat_agg_kernel<4, true, true><<<(N_NODES + 3) / 4, 128>>>(b1, nullptr);

    hgemm_attn_kernel<<<grid_sml, 256>>>(p_acth, W2, asrc2, adst2, N_NODES, 256, 64, 1);
    gat_agg_kernel<1, false, false><<<(N_NODES + 15) / 16, 128>>>(b2, p_act);

    pool_kernel<<<(N_NODES + PNB - 1) / PNB, 64>>>(batch, p_act);
    finalize_kernel<<<1, 64>>>(lin_w, lin_b, out);
}